// round 2
// baseline (speedup 1.0000x reference)
#include <cuda_runtime.h>
#include <math.h>

#define TT 2048
#define DD 2048
#define NH 16
#define NKV 4
#define HDIM 128
#define DQ 2048    // NH*HDIM
#define DKV 512    // NKV*HDIM
#define RDIM 1024  // D/2
#define EMA_L 128
#define EMA_NC 16

#define BETA 0.9f
#define ALPHA 0.1f
#define ATTN_SCALE 0.08838834764831843f  // 1/sqrt(128)

// ------------------- scratch (static device globals; no runtime alloc) -------------------
__device__ float g_l2[TT * DD];
__device__ float g_q[TT * DQ];
__device__ float g_h[TT * RDIM];
__device__ float g_fused[TT * DD];
__device__ float g_k[TT * DKV];
__device__ float g_v[TT * DKV];
__device__ float g_attn[TT * DQ];
__device__ float g_carry[EMA_NC * DD];
__device__ float g_prefix[EMA_NC * DD];

// ------------------- EMA: 3-pass exact chunked scan -------------------
__global__ void ema_local_kernel(const float* __restrict__ X) {
    int g = blockIdx.x * blockDim.x + threadIdx.x;  // 0 .. EMA_NC*DD-1
    int c = g / DD;
    int d = g % DD;
    float m = 0.f;
    int t0 = c * EMA_L;
#pragma unroll 4
    for (int i = 0; i < EMA_L; i++) {
        int t = t0 + i;
        m = fmaf(BETA, m, ALPHA * X[t * DD + d]);
        g_l2[t * DD + d] = m;
    }
    g_carry[c * DD + d] = m;
}

__global__ void ema_scan_kernel() {
    int d = blockIdx.x * blockDim.x + threadIdx.x;  // 0..DD-1
    // beta^EMA_L
    float bl = 1.f;
#pragma unroll
    for (int i = 0; i < EMA_L; i++) bl *= BETA;
    float m = 0.f;
#pragma unroll
    for (int c = 0; c < EMA_NC; c++) {
        g_prefix[c * DD + d] = m;                 // state entering chunk c
        m = fmaf(bl, m, g_carry[c * DD + d]);
    }
}

__global__ void ema_fix_kernel() {
    int g = blockIdx.x * blockDim.x + threadIdx.x;  // 0 .. (EMA_NC-1)*DD-1
    int c = g / DD + 1;
    int d = g % DD;
    float p = g_prefix[c * DD + d];
    float f = BETA;
    int t0 = c * EMA_L;
#pragma unroll 4
    for (int i = 0; i < EMA_L; i++) {
        int t = t0 + i;
        g_l2[t * DD + d] = fmaf(f, p, g_l2[t * DD + d]);
        f *= BETA;
    }
}

// ------------------- SGEMM: C = A(MxK) @ B(KxN), row-major, optional bias+silu -------------------
// 128x128 block tile, BK=8, 256 threads, 8x8 per thread.
template <int EPI>  // 0 = none, 1 = bias + silu
__global__ __launch_bounds__(256) void sgemm_kernel(
    const float* __restrict__ A, const float* __restrict__ B,
    const float* __restrict__ bias, float* __restrict__ C,
    int M, int N, int K)
{
    __shared__ float As[8][128];  // transposed A tile: As[k][m]
    __shared__ float Bs[8][128];

    const int bx = blockIdx.x;   // N tile
    const int by = blockIdx.y;   // M tile
    const int tid = threadIdx.x;
    const int tx = tid & 15;
    const int ty = tid >> 4;

    const int aRow = tid >> 1;          // 0..127
    const int aCol = (tid & 1) * 4;     // 0 or 4
    const int bRow = tid >> 5;          // 0..7
    const int bCol = (tid & 31) * 4;    // 0..124

    const float* Aptr = A + (size_t)(by * 128 + aRow) * K + aCol;
    const float* Bptr = B + (size_t)bRow * N + bx * 128 + bCol;

    float acc[8][8];
#pragma unroll
    for (int i = 0; i < 8; i++)
#pragma unroll
        for (int j = 0; j < 8; j++) acc[i][j] = 0.f;

    for (int k0 = 0; k0 < K; k0 += 8) {
        float4 a4 = *(const float4*)(Aptr + k0);
        float4 b4 = *(const float4*)(Bptr + (size_t)k0 * N);
        As[aCol + 0][aRow] = a4.x;
        As[aCol + 1][aRow] = a4.y;
        As[aCol + 2][aRow] = a4.z;
        As[aCol + 3][aRow] = a4.w;
        *(float4*)&Bs[bRow][bCol] = b4;
        __syncthreads();

#pragma unroll
        for (int k = 0; k < 8; k++) {
            float ra[8], rb[8];
#pragma unroll
            for (int i = 0; i < 8; i++) ra[i] = As[k][ty * 8 + i];
#pragma unroll
            for (int j = 0; j < 8; j++) rb[j] = Bs[k][tx * 8 + j];
#pragma unroll
            for (int i = 0; i < 8; i++)
#pragma unroll
                for (int j = 0; j < 8; j++)
                    acc[i][j] = fmaf(ra[i], rb[j], acc[i][j]);
        }
        __syncthreads();
    }

    // epilogue
#pragma unroll
    for (int i = 0; i < 8; i++) {
        int row = by * 128 + ty * 8 + i;
        int col0 = bx * 128 + tx * 8;
        float v[8];
#pragma unroll
        for (int j = 0; j < 8; j++) {
            float x = acc[i][j];
            if (EPI == 1) {
                x += bias[col0 + j];
                x = x / (1.f + __expf(-x));  // silu
            }
            v[j] = x;
        }
        float4* out0 = (float4*)&C[(size_t)row * N + col0];
        out0[0] = make_float4(v[0], v[1], v[2], v[3]);
        out0[1] = make_float4(v[4], v[5], v[6], v[7]);
    }
}

// ------------------- router: lam = softmax(h@Wr2 + br2); fused = lam0*x + lam1*l2 -------------------
__global__ __launch_bounds__(256) void router_fused_kernel(
    const float* __restrict__ X, const float* __restrict__ Wr2, const float* __restrict__ br2)
{
    const int t = blockIdx.x;
    const int tid = threadIdx.x;
    __shared__ float red[512];
    __shared__ float lam[2];

    float s0 = 0.f, s1 = 0.f;
    for (int j = tid; j < RDIM; j += 256) {
        float hv = g_h[t * RDIM + j];
        s0 = fmaf(hv, Wr2[2 * j + 0], s0);
        s1 = fmaf(hv, Wr2[2 * j + 1], s1);
    }
    red[tid] = s0;
    red[256 + tid] = s1;
    __syncthreads();
    for (int off = 128; off > 0; off >>= 1) {
        if (tid < off) {
            red[tid] += red[tid + off];
            red[256 + tid] += red[256 + tid + off];
        }
        __syncthreads();
    }
    if (tid == 0) {
        float a = red[0] + br2[0];
        float b = red[256] + br2[1];
        float mx = fmaxf(a, b);
        float e0 = __expf(a - mx), e1 = __expf(b - mx);
        float inv = 1.f / (e0 + e1);
        lam[0] = e0 * inv;
        lam[1] = e1 * inv;
    }
    __syncthreads();
    float l0 = lam[0], l1 = lam[1];
    for (int c = tid * 4; c < DD; c += 1024) {
        float4 x4 = *(const float4*)&X[t * DD + c];
        float4 m4 = *(const float4*)&g_l2[t * DD + c];
        float4 o;
        o.x = fmaf(l0, x4.x, l1 * m4.x);
        o.y = fmaf(l0, x4.y, l1 * m4.y);
        o.z = fmaf(l0, x4.z, l1 * m4.z);
        o.w = fmaf(l0, x4.w, l1 * m4.w);
        *(float4*)&g_fused[t * DD + c] = o;
    }
}

// ------------------- RoPE (in place) -------------------
__global__ void rope_kernel(float* __restrict__ M, int rowStride) {
    int t = blockIdx.x;
    int head = blockIdx.y;
    int i = threadIdx.x;  // 0..63
    double inv = pow(10000.0, -(double)i / 64.0);
    float ang = (float)((double)t * inv);
    float s, c;
    sincosf(ang, &s, &c);
    int base = t * rowStride + head * HDIM;
    float x1 = M[base + i];
    float x2 = M[base + 64 + i];
    M[base + i] = x1 * c - x2 * s;
    M[base + 64 + i] = fmaf(x2, c, x1 * s);
}

// ------------------- flash attention (causal GQA, fp32) -------------------
// grid: (T/64, NH). block: 256 threads (16x16). BQ=BK=64.
#define QS_LD 129
#define PS_LD 65
#define ATTN_SMEM_BYTES ((64 * QS_LD + 64 * QS_LD + 64 * 128 + 64 * PS_LD) * 4)

__global__ __launch_bounds__(256) void attn_kernel() {
    extern __shared__ float sm[];
    float* Qs = sm;                   // 64 x 129
    float* Ks = Qs + 64 * QS_LD;      // 64 x 129
    float* Vs = Ks + 64 * QS_LD;      // 64 x 128
    float* Ps = Vs + 64 * 128;        // 64 x 65

    const int qt = blockIdx.x;
    const int h = blockIdx.y;
    const int kvh = h >> 2;
    const int tid = threadIdx.x;
    const int tx = tid & 15;
    const int ty = tid >> 4;
    const int q0 = qt * 64;

    // load Q tile, folding softmax scale
    {
        int c4 = (tid & 31) * 4;
        for (int r = tid >> 5; r < 64; r += 8) {
            float4 v = *(const float4*)&g_q[(size_t)(q0 + r) * DQ + h * HDIM + c4];
            Qs[r * QS_LD + c4 + 0] = v.x * ATTN_SCALE;
            Qs[r * QS_LD + c4 + 1] = v.y * ATTN_SCALE;
            Qs[r * QS_LD + c4 + 2] = v.z * ATTN_SCALE;
            Qs[r * QS_LD + c4 + 3] = v.w * ATTN_SCALE;
        }
    }

    float m_i[4], l_i[4], accO[4][8];
#pragma unroll
    for (int i = 0; i < 4; i++) {
        m_i[i] = -1e30f;
        l_i[i] = 0.f;
#pragma unroll
        for (int j = 0; j < 8; j++) accO[i][j] = 0.f;
    }
    __syncthreads();

    const int nkt = qt + 1;
    for (int kt = 0; kt < nkt; kt++) {
        const int k0 = kt * 64;
        // load K, V tiles
        {
            int c4 = (tid & 31) * 4;
            for (int r = tid >> 5; r < 64; r += 8) {
                float4 kv = *(const float4*)&g_k[(size_t)(k0 + r) * DKV + kvh * HDIM + c4];
                Ks[r * QS_LD + c4 + 0] = kv.x;
                Ks[r * QS_LD + c4 + 1] = kv.y;
                Ks[r * QS_LD + c4 + 2] = kv.z;
                Ks[r * QS_LD + c4 + 3] = kv.w;
                float4 vv = *(const float4*)&g_v[(size_t)(k0 + r) * DKV + kvh * HDIM + c4];
                *(float4*)&Vs[r * 128 + c4] = vv;
            }
        }
        __syncthreads();

        // S = Q @ K^T (4x4 per thread)
        float s[4][4];
#pragma unroll
        for (int i = 0; i < 4; i++)
#pragma unroll
            for (int j = 0; j < 4; j++) s[i][j] = 0.f;

#pragma unroll 4
        for (int kk = 0; kk < HDIM; kk++) {
            float qa[4], kb[4];
#pragma unroll
            for (int i = 0; i < 4; i++) qa[i] = Qs[(4 * ty + i) * QS_LD + kk];
#pragma unroll
            for (int j = 0; j < 4; j++) kb[j] = Ks[(4 * tx + j) * QS_LD + kk];
#pragma unroll
            for (int i = 0; i < 4; i++)
#pragma unroll
                for (int j = 0; j < 4; j++) s[i][j] = fmaf(qa[i], kb[j], s[i][j]);
        }

        // causal mask (diagonal tile only)
        if (kt == qt) {
#pragma unroll
            for (int i = 0; i < 4; i++)
#pragma unroll
                for (int j = 0; j < 4; j++)
                    if (4 * tx + j > 4 * ty + i) s[i][j] = -1e30f;
        }

        // online softmax
        float rowm[4], rs[4];
#pragma unroll
        for (int i = 0; i < 4; i++) {
            float mx = s[i][0];
#pragma unroll
            for (int j = 1; j < 4; j++) mx = fmaxf(mx, s[i][j]);
            rowm[i] = mx;
        }
#pragma unroll
        for (int off = 1; off < 16; off <<= 1)
#pragma unroll
            for (int i = 0; i < 4; i++)
                rowm[i] = fmaxf(rowm[i], __shfl_xor_sync(0xffffffffu, rowm[i], off));

#pragma unroll
        for (int i = 0; i < 4; i++) {
            float newm = fmaxf(m_i[i], rowm[i]);
            float sum = 0.f;
#pragma unroll
            for (int j = 0; j < 4; j++) {
                s[i][j] = __expf(s[i][j] - newm);
                sum += s[i][j];
            }
            rs[i] = sum;
            float corr = __expf(m_i[i] - newm);
            m_i[i] = newm;
            l_i[i] *= corr;
#pragma unroll
            for (int j = 0; j < 8; j++) accO[i][j] *= corr;
        }
#pragma unroll
        for (int off = 1; off < 16; off <<= 1)
#pragma unroll
            for (int i = 0; i < 4; i++)
                rs[i] += __shfl_xor_sync(0xffffffffu, rs[i], off);
#pragma unroll
        for (int i = 0; i < 4; i++) l_i[i] += rs[i];

        // write P to smem
#pragma unroll
        for (int i = 0; i < 4; i++)
#pragma unroll
            for (int j = 0; j < 4; j++)
                Ps[(4 * ty + i) * PS_LD + 4 * tx + j] = s[i][j];
        __syncthreads();

        // O += P @ V  (4 rows x 8 cols per thread)
#pragma unroll 4
        for (int k = 0; k < 64; k++) {
            float pa[4];
#pragma unroll
            for (int i = 0; i < 4; i++) pa[i] = Ps[(4 * ty + i) * PS_LD + k];
            float vb[8];
#pragma unroll
            for (int j = 0; j < 8; j++) vb[j] = Vs[k * 128 + 8 * tx + j];
#pragma unroll
            for (int i = 0; i < 4; i++)
#pragma unroll
                for (int j = 0; j < 8; j++)
                    accO[i][j] = fmaf(pa[i], vb[j], accO[i][j]);
        }
        __syncthreads();
    }

    // write output
#pragma unroll
    for (int i = 0; i < 4; i++) {
        float inv = 1.f / l_i[i];
        int row = q0 + 4 * ty + i;
        float* outp = &g_attn[(size_t)row * DQ + h * HDIM + 8 * tx];
        float4 o0 = make_float4(accO[i][0] * inv, accO[i][1] * inv, accO[i][2] * inv, accO[i][3] * inv);
        float4 o1 = make_float4(accO[i][4] * inv, accO[i][5] * inv, accO[i][6] * inv, accO[i][7] * inv);
        *(float4*)&outp[0] = o0;
        *(float4*)&outp[4] = o1;
    }
}

// ------------------- host launch -------------------
extern "C" void kernel_launch(void* const* d_in, const int* in_sizes, int n_in,
                              void* d_out, int out_size) {
    const float* X   = (const float*)d_in[0];
    const float* Wq  = (const float*)d_in[1];
    const float* Wk  = (const float*)d_in[2];
    const float* Wv  = (const float*)d_in[3];
    const float* Wo  = (const float*)d_in[4];
    const float* Wr1 = (const float*)d_in[5];
    const float* br1 = (const float*)d_in[6];
    const float* Wr2 = (const float*)d_in[7];
    const float* br2 = (const float*)d_in[8];
    float* out = (float*)d_out;

    float *p_q, *p_h, *p_fused, *p_k, *p_v, *p_attn;
    cudaGetSymbolAddress((void**)&p_q, g_q);
    cudaGetSymbolAddress((void**)&p_h, g_h);
    cudaGetSymbolAddress((void**)&p_fused, g_fused);
    cudaGetSymbolAddress((void**)&p_k, g_k);
    cudaGetSymbolAddress((void**)&p_v, g_v);
    cudaGetSymbolAddress((void**)&p_attn, g_attn);

    cudaFuncSetAttribute(attn_kernel, cudaFuncAttributeMaxDynamicSharedMemorySize, ATTN_SMEM_BYTES);

    // EMA (3-pass exact scan)
    ema_local_kernel<<<(EMA_NC * DD) / 256, 256>>>(X);
    ema_scan_kernel<<<DD / 256, 256>>>();
    ema_fix_kernel<<<((EMA_NC - 1) * DD) / 256, 256>>>();

    // q = X @ Wq
    sgemm_kernel<0><<<dim3(DQ / 128, TT / 128), 256>>>(X, Wq, nullptr, p_q, TT, DQ, DD);
    // h = silu(q @ Wr1 + br1)
    sgemm_kernel<1><<<dim3(RDIM / 128, TT / 128), 256>>>(p_q, Wr1, br1, p_h, TT, RDIM, DQ);
    // lam + fused
    router_fused_kernel<<<TT, 256>>>(X, Wr2, br2);
    // k, v
    sgemm_kernel<0><<<dim3(DKV / 128, TT / 128), 256>>>(p_fused, Wk, nullptr, p_k, TT, DKV, DD);
    sgemm_kernel<0><<<dim3(DKV / 128, TT / 128), 256>>>(p_fused, Wv, nullptr, p_v, TT, DKV, DD);
    // RoPE (q after router consumed it)
    rope_kernel<<<dim3(TT, NH), 64>>>(p_q, DQ);
    rope_kernel<<<dim3(TT, NKV), 64>>>(p_k, DKV);
    // attention
    attn_kernel<<<dim3(TT / 64, NH), 256, ATTN_SMEM_BYTES>>>();
    // out = attn @ Wo
    sgemm_kernel<0><<<dim3(DD / 128, TT / 128), 256>>>(p_attn, Wo, nullptr, out, TT, DD, DQ);
}

// round 6
// speedup vs baseline: 2.5115x; 2.5115x over previous
#include <cuda_runtime.h>
#include <math.h>
#include <stdint.h>

#define TT 2048
#define DD 2048
#define NH 16
#define NKV 4
#define HDIM 128
#define DQ 2048    // NH*HDIM
#define DKV 512    // NKV*HDIM
#define RDIM 1024  // D/2
#define EMA_L 128
#define EMA_NC 16

#define BETA 0.9f
#define ALPHA 0.1f
#define ATTN_SCALE 0.08838834764831843f  // 1/sqrt(128)

// ------------------- scratch -------------------
__device__ float g_l2[TT * DD];
__device__ float g_q[TT * DQ];
__device__ float g_h[TT * RDIM];
__device__ float g_fused[TT * DD];
__device__ float g_k[TT * DKV];
__device__ float g_v[TT * DKV];
__device__ float g_attn[TT * DQ];
__device__ float g_carry[EMA_NC * DD];
__device__ float g_prefix[EMA_NC * DD];

// ------------------- tf32 helpers -------------------
__device__ __forceinline__ uint32_t f2tf(float f) {
    uint32_t u;
    asm("cvt.rna.tf32.f32 %0, %1;" : "=r"(u) : "f"(f));
    return u;
}
__device__ __forceinline__ void mma8(float* c, const uint32_t* a, uint32_t b0, uint32_t b1) {
    asm volatile(
        "mma.sync.aligned.m16n8k8.row.col.f32.tf32.tf32.f32 "
        "{%0,%1,%2,%3}, {%4,%5,%6,%7}, {%8,%9}, {%0,%1,%2,%3};\n"
        : "+f"(c[0]), "+f"(c[1]), "+f"(c[2]), "+f"(c[3])
        : "r"(a[0]), "r"(a[1]), "r"(a[2]), "r"(a[3]), "r"(b0), "r"(b1));
}

// ------------------- EMA: 3-pass exact chunked scan -------------------
__global__ void ema_local_kernel(const float* __restrict__ X) {
    int g = blockIdx.x * blockDim.x + threadIdx.x;
    int c = g / DD;
    int d = g % DD;
    float m = 0.f;
    int t0 = c * EMA_L;
#pragma unroll 4
    for (int i = 0; i < EMA_L; i++) {
        int t = t0 + i;
        m = fmaf(BETA, m, ALPHA * X[t * DD + d]);
        g_l2[t * DD + d] = m;
    }
    g_carry[c * DD + d] = m;
}

__global__ void ema_scan_kernel() {
    int d = blockIdx.x * blockDim.x + threadIdx.x;
    float bl = 1.f;
#pragma unroll
    for (int i = 0; i < EMA_L; i++) bl *= BETA;
    float m = 0.f;
#pragma unroll
    for (int c = 0; c < EMA_NC; c++) {
        g_prefix[c * DD + d] = m;
        m = fmaf(bl, m, g_carry[c * DD + d]);
    }
}

__global__ void ema_fix_kernel() {
    int g = blockIdx.x * blockDim.x + threadIdx.x;
    int c = g / DD + 1;
    int d = g % DD;
    float p = g_prefix[c * DD + d];
    float f = BETA;
    int t0 = c * EMA_L;
#pragma unroll 4
    for (int i = 0; i < EMA_L; i++) {
        int t = t0 + i;
        g_l2[t * DD + d] = fmaf(f, p, g_l2[t * DD + d]);
        f *= BETA;
    }
}

// ------------------- TF32 GEMM: C = A(MxK) @ B(KxN) row-major -------------------
// block 128x128, BK=32, 256 threads, 8 warps (2m x 4n), warp tile 64x32.
#define AP 36   // A smem pad (cols per row)
#define BP 132  // B smem pad

template <int EPI>  // 0 = none, 1 = bias + silu
__global__ __launch_bounds__(256) void mm_tf32(
    const float* __restrict__ A, const float* __restrict__ B,
    const float* __restrict__ bias, float* __restrict__ C,
    int M, int N, int K)
{
    __shared__ uint32_t As[128 * AP];
    __shared__ uint32_t Bs[32 * BP];

    const int tid = threadIdx.x;
    const int bx = blockIdx.x, by = blockIdx.y;

    // global load mapping
    const int arow = tid >> 3;          // 0..31 (stride 32 x4)
    const int acol = (tid & 7) * 4;     // 0..28
    const int brow = tid >> 5;          // 0..7 (stride 8 x4)
    const int bcol = (tid & 31) * 4;    // 0..124

    const float* Ag = A + (size_t)(by * 128 + arow) * K + acol;
    const float* Bg = B + (size_t)brow * N + (size_t)bx * 128 + bcol;

    // warp/lane mapping for mma
    const int lane = tid & 31;
    const int wid = tid >> 5;
    const int wm = wid >> 2;        // 0..1
    const int wn = wid & 3;         // 0..3
    const int m0 = wm * 64;
    const int n0 = wn * 32;
    const int g = lane >> 2;        // 0..7
    const int q = lane & 3;         // 0..3

    float4 a_st[4], b_st[4];
#pragma unroll
    for (int u = 0; u < 4; u++) a_st[u] = *(const float4*)(Ag + (size_t)(u * 32) * K);
#pragma unroll
    for (int u = 0; u < 4; u++) b_st[u] = *(const float4*)(Bg + (size_t)(u * 8) * N);

    // store tile 0
#pragma unroll
    for (int u = 0; u < 4; u++) {
        uint4 av;
        av.x = f2tf(a_st[u].x); av.y = f2tf(a_st[u].y);
        av.z = f2tf(a_st[u].z); av.w = f2tf(a_st[u].w);
        *(uint4*)&As[(arow + u * 32) * AP + acol] = av;
        uint4 bv;
        bv.x = f2tf(b_st[u].x); bv.y = f2tf(b_st[u].y);
        bv.z = f2tf(b_st[u].z); bv.w = f2tf(b_st[u].w);
        *(uint4*)&Bs[(brow + u * 8) * BP + bcol] = bv;
    }
    __syncthreads();

    float acc[4][4][4];
#pragma unroll
    for (int i = 0; i < 4; i++)
#pragma unroll
        for (int j = 0; j < 4; j++)
#pragma unroll
            for (int c = 0; c < 4; c++) acc[i][j][c] = 0.f;

    const int iters = K / 32;
    for (int it = 0; it < iters; it++) {
        if (it + 1 < iters) {
            const float* Ag2 = Ag + (it + 1) * 32;
            const float* Bg2 = Bg + (size_t)(it + 1) * 32 * N;
#pragma unroll
            for (int u = 0; u < 4; u++) a_st[u] = *(const float4*)(Ag2 + (size_t)(u * 32) * K);
#pragma unroll
            for (int u = 0; u < 4; u++) b_st[u] = *(const float4*)(Bg2 + (size_t)(u * 8) * N);
        }

#pragma unroll
        for (int kk = 0; kk < 4; kk++) {
            const int ks = kk * 8;
            uint32_t af[4][4], bf[4][2];
#pragma unroll
            for (int i = 0; i < 4; i++) {
                const int mr = m0 + i * 16 + g;
                af[i][0] = As[mr * AP + ks + q];
                af[i][1] = As[(mr + 8) * AP + ks + q];
                af[i][2] = As[mr * AP + ks + q + 4];
                af[i][3] = As[(mr + 8) * AP + ks + q + 4];
            }
#pragma unroll
            for (int j = 0; j < 4; j++) {
                const int nc = n0 + j * 8 + g;
                bf[j][0] = Bs[(ks + q) * BP + nc];
                bf[j][1] = Bs[(ks + q + 4) * BP + nc];
            }
#pragma unroll
            for (int i = 0; i < 4; i++)
#pragma unroll
                for (int j = 0; j < 4; j++)
                    mma8(acc[i][j], af[i], bf[j][0], bf[j][1]);
        }

        if (it + 1 < iters) {
            __syncthreads();
#pragma unroll
            for (int u = 0; u < 4; u++) {
                uint4 av;
                av.x = f2tf(a_st[u].x); av.y = f2tf(a_st[u].y);
                av.z = f2tf(a_st[u].z); av.w = f2tf(a_st[u].w);
                *(uint4*)&As[(arow + u * 32) * AP + acol] = av;
                uint4 bv;
                bv.x = f2tf(b_st[u].x); bv.y = f2tf(b_st[u].y);
                bv.z = f2tf(b_st[u].z); bv.w = f2tf(b_st[u].w);
                *(uint4*)&Bs[(brow + u * 8) * BP + bcol] = bv;
            }
            __syncthreads();
        }
    }

    // epilogue
#pragma unroll
    for (int i = 0; i < 4; i++) {
#pragma unroll
        for (int j = 0; j < 4; j++) {
            const int row0 = by * 128 + m0 + i * 16 + g;
            const int col = bx * 128 + n0 + j * 8 + 2 * q;
            float v0 = acc[i][j][0], v1 = acc[i][j][1];
            float v2 = acc[i][j][2], v3 = acc[i][j][3];
            if (EPI == 1) {
                float b0v = bias[col], b1v = bias[col + 1];
                v0 += b0v; v1 += b1v; v2 += b0v; v3 += b1v;
                v0 = v0 / (1.f + __expf(-v0));
                v1 = v1 / (1.f + __expf(-v1));
                v2 = v2 / (1.f + __expf(-v2));
                v3 = v3 / (1.f + __expf(-v3));
            }
            *(float2*)&C[(size_t)row0 * N + col] = make_float2(v0, v1);
            *(float2*)&C[(size_t)(row0 + 8) * N + col] = make_float2(v2, v3);
        }
    }
}

// ------------------- router -------------------
__global__ __launch_bounds__(256) void router_fused_kernel(
    const float* __restrict__ X, const float* __restrict__ Wr2, const float* __restrict__ br2)
{
    const int t = blockIdx.x;
    const int tid = threadIdx.x;
    __shared__ float red[512];
    __shared__ float lam[2];

    float s0 = 0.f, s1 = 0.f;
    for (int j = tid; j < RDIM; j += 256) {
        float hv = g_h[t * RDIM + j];
        s0 = fmaf(hv, Wr2[2 * j + 0], s0);
        s1 = fmaf(hv, Wr2[2 * j + 1], s1);
    }
    red[tid] = s0;
    red[256 + tid] = s1;
    __syncthreads();
    for (int off = 128; off > 0; off >>= 1) {
        if (tid < off) {
            red[tid] += red[tid + off];
            red[256 + tid] += red[256 + tid + off];
        }
        __syncthreads();
    }
    if (tid == 0) {
        float a = red[0] + br2[0];
        float b = red[256] + br2[1];
        float mx = fmaxf(a, b);
        float e0 = __expf(a - mx), e1 = __expf(b - mx);
        float inv = 1.f / (e0 + e1);
        lam[0] = e0 * inv;
        lam[1] = e1 * inv;
    }
    __syncthreads();
    float l0 = lam[0], l1 = lam[1];
    for (int c = tid * 4; c < DD; c += 1024) {
        float4 x4 = *(const float4*)&X[t * DD + c];
        float4 m4 = *(const float4*)&g_l2[t * DD + c];
        float4 o;
        o.x = fmaf(l0, x4.x, l1 * m4.x);
        o.y = fmaf(l0, x4.y, l1 * m4.y);
        o.z = fmaf(l0, x4.z, l1 * m4.z);
        o.w = fmaf(l0, x4.w, l1 * m4.w);
        *(float4*)&g_fused[t * DD + c] = o;
    }
}

// ------------------- RoPE (in place) -------------------
__global__ void rope_kernel(float* __restrict__ M, int rowStride) {
    int t = blockIdx.x;
    int head = blockIdx.y;
    int i = threadIdx.x;  // 0..63
    double inv = pow(10000.0, -(double)i / 64.0);
    float ang = (float)((double)t * inv);
    float s, c;
    sincosf(ang, &s, &c);
    int base = t * rowStride + head * HDIM;
    float x1 = M[base + i];
    float x2 = M[base + 64 + i];
    M[base + i] = x1 * c - x2 * s;
    M[base + 64 + i] = fmaf(x2, c, x1 * s);
}

// ------------------- flash attention (causal GQA, tf32 mma) -------------------
// grid (T/64, NH), 128 threads (4 warps); warp w owns q-rows [16w,16w+16).
#define KPAD 132
#define PPAD 68
#define ATTN_SMEM_WORDS (64 * KPAD * 2 + 64 * PPAD)
#define ATTN_SMEM_BYTES (ATTN_SMEM_WORDS * 4)

__global__ __launch_bounds__(128) void attn_kernel() {
    extern __shared__ uint32_t smw[];
    uint32_t* Ks = smw;                 // 64 x 132 (tf32)
    uint32_t* Vs = Ks + 64 * KPAD;      // 64 x 132 (tf32)
    uint32_t* Ps = Vs + 64 * KPAD;      // 64 x 68  (tf32)

    const int qt = blockIdx.x;
    const int h = blockIdx.y;
    const int kvh = h >> 2;
    const int tid = threadIdx.x;
    const int lane = tid & 31;
    const int wid = tid >> 5;          // 0..3
    const int g = lane >> 2;           // 0..7
    const int q = lane & 3;            // 0..3
    const int q0 = qt * 64;
    const int m0 = wid * 16;

    // ---- stage Q (scaled) into Ks, then load persistent Q fragments ----
    for (int idx = tid; idx < 2048; idx += 128) {
        int r = idx >> 5;
        int c4 = (idx & 31) << 2;
        float4 v = *(const float4*)&g_q[(size_t)(q0 + r) * DQ + h * HDIM + c4];
        uint4 u;
        u.x = f2tf(v.x * ATTN_SCALE); u.y = f2tf(v.y * ATTN_SCALE);
        u.z = f2tf(v.z * ATTN_SCALE); u.w = f2tf(v.w * ATTN_SCALE);
        *(uint4*)&Ks[r * KPAD + c4] = u;
    }
    __syncthreads();

    uint32_t qf[16][4];
#pragma unroll
    for (int kk = 0; kk < 16; kk++) {
        const int base = (m0 + g) * KPAD + kk * 8 + q;
        qf[kk][0] = Ks[base];
        qf[kk][1] = Ks[base + 8 * KPAD];
        qf[kk][2] = Ks[base + 4];
        qf[kk][3] = Ks[base + 8 * KPAD + 4];
    }
    __syncthreads();

    float oacc[16][4];
#pragma unroll
    for (int n = 0; n < 16; n++)
#pragma unroll
        for (int c = 0; c < 4; c++) oacc[n][c] = 0.f;
    float mrow[2] = {-1e30f, -1e30f};
    float lrow[2] = {0.f, 0.f};

    for (int kt = 0; kt <= qt; kt++) {
        const int k0 = kt * 64;
        // load K, V tiles (fp32 -> tf32)
        for (int idx = tid; idx < 2048; idx += 128) {
            int r = idx >> 5;
            int c4 = (idx & 31) << 2;
            float4 kv = *(const float4*)&g_k[(size_t)(k0 + r) * DKV + kvh * HDIM + c4];
            uint4 ku;
            ku.x = f2tf(kv.x); ku.y = f2tf(kv.y); ku.z = f2tf(kv.z); ku.w = f2tf(kv.w);
            *(uint4*)&Ks[r * KPAD + c4] = ku;
            float4 vv = *(const float4*)&g_v[(size_t)(k0 + r) * DKV + kvh * HDIM + c4];
            uint4 vu;
            vu.x = f2tf(vv.x); vu.y = f2tf(vv.y); vu.z = f2tf(vv.z); vu.w = f2tf(vv.w);
            *(uint4*)&Vs[r * KPAD + c4] = vu;
        }
        __syncthreads();

        // ---- S = Q @ K^T : per warp 16 x 64 ----
        float sacc[8][4];
#pragma unroll
        for (int n = 0; n < 8; n++) {
#pragma unroll
            for (int c = 0; c < 4; c++) sacc[n][c] = 0.f;
            const int bb = (n * 8 + g) * KPAD + q;
#pragma unroll
            for (int kk = 0; kk < 16; kk++) {
                uint32_t b0 = Ks[bb + kk * 8];
                uint32_t b1 = Ks[bb + kk * 8 + 4];
                mma8(sacc[n], qf[kk], b0, b1);
            }
        }

        // ---- causal mask (diagonal tile) ----
        if (kt == qt) {
#pragma unroll
            for (int n = 0; n < 8; n++) {
                const int col0 = n * 8 + 2 * q;
                const int rA = m0 + g, rB = m0 + g + 8;
                if (col0 > rA) sacc[n][0] = -1e30f;
                if (col0 + 1 > rA) sacc[n][1] = -1e30f;
                if (col0 > rB) sacc[n][2] = -1e30f;
                if (col0 + 1 > rB) sacc[n][3] = -1e30f;
            }
        }

        // ---- online softmax (per thread: rows g and g+8) ----
        float mx0 = -1e30f, mx1 = -1e30f;
#pragma unroll
        for (int n = 0; n < 8; n++) {
            mx0 = fmaxf(mx0, fmaxf(sacc[n][0], sacc[n][1]));
            mx1 = fmaxf(mx1, fmaxf(sacc[n][2], sacc[n][3]));
        }
        mx0 = fmaxf(mx0, __shfl_xor_sync(0xffffffffu, mx0, 1));
        mx0 = fmaxf(mx0, __shfl_xor_sync(0xffffffffu, mx0, 2));
        mx1 = fmaxf(mx1, __shfl_xor_sync(0xffffffffu, mx1, 1));
        mx1 = fmaxf(mx1, __shfl_xor_sync(0xffffffffu, mx1, 2));

        const float nm0 = fmaxf(mrow[0], mx0);
        const float nm1 = fmaxf(mrow[1], mx1);
        const float corr0 = __expf(mrow[0] - nm0);
        const float corr1 = __expf(mrow[1] - nm1);
        float rs0 = 0.f, rs1 = 0.f;
#pragma unroll
        for (int n = 0; n < 8; n++) {
            sacc[n][0] = __expf(sacc[n][0] - nm0);
            sacc[n][1] = __expf(sacc[n][1] - nm0);
            sacc[n][2] = __expf(sacc[n][2] - nm1);
            sacc[n][3] = __expf(sacc[n][3] - nm1);
            rs0 += sacc[n][0] + sacc[n][1];
            rs1 += sacc[n][2] + sacc[n][3];
        }
        rs0 += __shfl_xor_sync(0xffffffffu, rs0, 1);
        rs0 += __shfl_xor_sync(0xffffffffu, rs0, 2);
        rs1 += __shfl_xor_sync(0xffffffffu, rs1, 1);
        rs1 += __shfl_xor_sync(0xffffffffu, rs1, 2);
        lrow[0] = lrow[0] * corr0 + rs0;
        lrow[1] = lrow[1] * corr1 + rs1;
        mrow[0] = nm0;
        mrow[1] = nm1;
#pragma unroll
        for (int n = 0; n < 16; n++) {
            oacc[n][0] *= corr0;
            oacc[n][1] *= corr0;
            oacc[n][2] *= corr1;
            oacc[n][3] *= corr1;
        }

        // ---- store P (tf32) to smem ----
#pragma unroll
        for (int n = 0; n < 8; n++) {
            const int col = n * 8 + 2 * q;
            Ps[(m0 + g) * PPAD + col] = f2tf(sacc[n][0]);
            Ps[(m0 + g) * PPAD + col + 1] = f2tf(sacc[n][1]);
            Ps[(m0 + g + 8) * PPAD + col] = f2tf(sacc[n][2]);
            Ps[(m0 + g + 8) * PPAD + col + 1] = f2tf(sacc[n][3]);
        }
        __syncwarp();

        // ---- O += P @ V : per warp 16 x 128 ----
#pragma unroll
        for (int kk = 0; kk < 8; kk++) {
            uint32_t pa[4];
            const int pb = (m0 + g) * PPAD + kk * 8 + q;
            pa[0] = Ps[pb];
            pa[1] = Ps[pb + 8 * PPAD];
            pa[2] = Ps[pb + 4];
            pa[3] = Ps[pb + 8 * PPAD + 4];
            const int vb = (kk * 8 + q) * KPAD + g;
#pragma unroll
            for (int n = 0; n < 16; n++) {
                uint32_t b0 = Vs[vb + n * 8];
                uint32_t b1 = Vs[vb + 4 * KPAD + n * 8];
                mma8(oacc[n], pa, b0, b1);
            }
        }
        __syncthreads();
    }

    // ---- write O / l ----
    const float inv0 = 1.f / lrow[0];
    const float inv1 = 1.f / lrow[1];
    const int rowA = q0 + m0 + g;
    const int rowB = rowA + 8;
#pragma unroll
    for (int n = 0; n < 16; n++) {
        const int col = h * HDIM + n * 8 + 2 * q;
        *(float2*)&g_attn[(size_t)rowA * DQ + col] =
            make_float2(oacc[n][0] * inv0, oacc[n][1] * inv0);
        *(float2*)&g_attn[(size_t)rowB * DQ + col] =
            make_float2(oacc[n][2] * inv1, oacc[n][3] * inv1);
    }
}

// ------------------- host launch -------------------
extern "C" void kernel_launch(void* const* d_in, const int* in_sizes, int n_in,
                              void* d_out, int out_size) {
    const float* X   = (const float*)d_in[0];
    const float* Wq  = (const float*)d_in[1];
    const float* Wk  = (const float*)d_in[2];
    const float* Wv  = (const float*)d_in[3];
    const float* Wo  = (const float*)d_in[4];
    const float* Wr1 = (const float*)d_in[5];
    const float* br1 = (const float*)d_in[6];
    const float* Wr2 = (const float*)d_in[7];
    const float* br2 = (const float*)d_in[8];
    float* out = (float*)d_out;

    float *p_q, *p_h, *p_fused, *p_k, *p_v, *p_attn;
    cudaGetSymbolAddress((void**)&p_q, g_q);
    cudaGetSymbolAddress((void**)&p_h, g_h);
    cudaGetSymbolAddress((void**)&p_fused, g_fused);
    cudaGetSymbolAddress((void**)&p_k, g_k);
    cudaGetSymbolAddress((void**)&p_v, g_v);
    cudaGetSymbolAddress((void**)&p_attn, g_attn);

    cudaFuncSetAttribute(attn_kernel, cudaFuncAttributeMaxDynamicSharedMemorySize, ATTN_SMEM_BYTES);

    // EMA
    ema_local_kernel<<<(EMA_NC * DD) / 256, 256>>>(X);
    ema_scan_kernel<<<DD / 256, 256>>>();
    ema_fix_kernel<<<((EMA_NC - 1) * DD) / 256, 256>>>();

    // q = X @ Wq
    mm_tf32<0><<<dim3(DQ / 128, TT / 128), 256>>>(X, Wq, nullptr, p_q, TT, DQ, DD);
    // h = silu(q @ Wr1 + br1)
    mm_tf32<1><<<dim3(RDIM / 128, TT / 128), 256>>>(p_q, Wr1, br1, p_h, TT, RDIM, DQ);
    // lam + fused
    router_fused_kernel<<<TT, 256>>>(X, Wr2, br2);
    // k, v
    mm_tf32<0><<<dim3(DKV / 128, TT / 128), 256>>>(p_fused, Wk, nullptr, p_k, TT, DKV, DD);
    mm_tf32<0><<<dim3(DKV / 128, TT / 128), 256>>>(p_fused, Wv, nullptr, p_v, TT, DKV, DD);
    // RoPE
    rope_kernel<<<dim3(TT, NH), 64>>>(p_q, DQ);
    rope_kernel<<<dim3(TT, NKV), 64>>>(p_k, DKV);
    // attention
    attn_kernel<<<dim3(TT / 64, NH), 128, ATTN_SMEM_BYTES>>>();
    // out = attn @ Wo
    mm_tf32<0><<<dim3(DD / 128, TT / 128), 256>>>(p_attn, Wo, nullptr, out, TT, DD, DQ);
}

// round 8
// speedup vs baseline: 2.6528x; 1.0563x over previous
#include <cuda_runtime.h>
#include <math.h>
#include <stdint.h>

#define TT 2048
#define DD 2048
#define NH 16
#define NKV 4
#define HDIM 128
#define DQ 2048    // NH*HDIM
#define DKV 512    // NKV*HDIM
#define RDIM 1024  // D/2
#define EMA_L 128
#define EMA_NC 16

#define BETA 0.9f
#define ALPHA 0.1f
#define ATTN_SCALE 0.08838834764831843f  // 1/sqrt(128)

// ------------------- scratch -------------------
__device__ float g_l2[TT * DD];
__device__ float g_q[TT * DQ];
__device__ float g_h[TT * RDIM];
__device__ float g_fused[TT * DD];
__device__ float g_k[TT * DKV];
__device__ float g_v[TT * DKV];
__device__ float g_attn[TT * DQ];
__device__ float g_carry[EMA_NC * DD];
__device__ float g_prefix[EMA_NC * DD];

// ------------------- tf32 / async helpers -------------------
__device__ __forceinline__ uint32_t f2tf(float f) {
    uint32_t u;
    asm("cvt.rna.tf32.f32 %0, %1;" : "=r"(u) : "f"(f));
    return u;
}
__device__ __forceinline__ void mma8(float* c, const uint32_t* a, uint32_t b0, uint32_t b1) {
    asm volatile(
        "mma.sync.aligned.m16n8k8.row.col.f32.tf32.tf32.f32 "
        "{%0,%1,%2,%3}, {%4,%5,%6,%7}, {%8,%9}, {%0,%1,%2,%3};\n"
        : "+f"(c[0]), "+f"(c[1]), "+f"(c[2]), "+f"(c[3])
        : "r"(a[0]), "r"(a[1]), "r"(a[2]), "r"(a[3]), "r"(b0), "r"(b1));
}
__device__ __forceinline__ uint32_t smem_u32(const void* p) {
    uint32_t a;
    asm("{ .reg .u64 t; cvta.to.shared.u64 t, %1; cvt.u32.u64 %0, t; }" : "=r"(a) : "l"(p));
    return a;
}
__device__ __forceinline__ void cpasync16(uint32_t dst, const void* src) {
    asm volatile("cp.async.ca.shared.global [%0], [%1], 16;\n" :: "r"(dst), "l"(src));
}
#define CP_COMMIT() asm volatile("cp.async.commit_group;\n" ::: "memory")
#define CP_WAIT(N) asm volatile("cp.async.wait_group %0;\n" :: "n"(N) : "memory")

// ------------------- EMA: 3-pass exact chunked scan -------------------
__global__ void ema_local_kernel(const float* __restrict__ X) {
    int g = blockIdx.x * blockDim.x + threadIdx.x;
    int c = g / DD;
    int d = g % DD;
    float m = 0.f;
    int t0 = c * EMA_L;
#pragma unroll 4
    for (int i = 0; i < EMA_L; i++) {
        int t = t0 + i;
        m = fmaf(BETA, m, ALPHA * X[t * DD + d]);
        g_l2[t * DD + d] = m;
    }
    g_carry[c * DD + d] = m;
}

__global__ void ema_scan_kernel() {
    int d = blockIdx.x * blockDim.x + threadIdx.x;
    float bl = 1.f;
#pragma unroll
    for (int i = 0; i < EMA_L; i++) bl *= BETA;
    float m = 0.f;
#pragma unroll
    for (int c = 0; c < EMA_NC; c++) {
        g_prefix[c * DD + d] = m;
        m = fmaf(bl, m, g_carry[c * DD + d]);
    }
}

__global__ void ema_fix_kernel() {
    int g = blockIdx.x * blockDim.x + threadIdx.x;
    int c = g / DD + 1;
    int d = g % DD;
    float p = g_prefix[c * DD + d];
    float f = BETA;
    int t0 = c * EMA_L;
#pragma unroll 4
    for (int i = 0; i < EMA_L; i++) {
        int t = t0 + i;
        g_l2[t * DD + d] = fmaf(f, p, g_l2[t * DD + d]);
        f *= BETA;
    }
}

// ------------------- TF32 GEMM: C = A(MxK) @ B(KxN) row-major -------------------
// block 128x128, BK=32, 256 threads, 8 warps (2m x 4n), warp tile 64x32.
#define AP 36   // A smem pad
#define BP 132  // B smem pad

// EPI: 0 = none, 1 = bias + silu, 2 = store tf32-rounded
template <int EPI>
__global__ __launch_bounds__(256, 2) void mm_tf32(
    const float* __restrict__ A, const float* __restrict__ B,
    const float* __restrict__ bias, float* __restrict__ C,
    int M, int N, int K)
{
    __shared__ uint32_t As[128 * AP];
    __shared__ uint32_t Bs[32 * BP];

    const int tid = threadIdx.x;
    const int bx = blockIdx.x, by = blockIdx.y;

    const int arow = tid >> 3;
    const int acol = (tid & 7) * 4;
    const int brow = tid >> 5;
    const int bcol = (tid & 31) * 4;

    const float* Ag = A + (size_t)(by * 128 + arow) * K + acol;
    const float* Bg = B + (size_t)brow * N + (size_t)bx * 128 + bcol;

    const int lane = tid & 31;
    const int wid = tid >> 5;
    const int wm = wid >> 2;
    const int wn = wid & 3;
    const int m0 = wm * 64;
    const int n0 = wn * 32;
    const int g = lane >> 2;
    const int q = lane & 3;

    float4 a_st[4], b_st[4];
#pragma unroll
    for (int u = 0; u < 4; u++) a_st[u] = *(const float4*)(Ag + (size_t)(u * 32) * K);
#pragma unroll
    for (int u = 0; u < 4; u++) b_st[u] = *(const float4*)(Bg + (size_t)(u * 8) * N);

#pragma unroll
    for (int u = 0; u < 4; u++) {
        uint4 av;
        av.x = f2tf(a_st[u].x); av.y = f2tf(a_st[u].y);
        av.z = f2tf(a_st[u].z); av.w = f2tf(a_st[u].w);
        *(uint4*)&As[(arow + u * 32) * AP + acol] = av;
        uint4 bv;
        bv.x = f2tf(b_st[u].x); bv.y = f2tf(b_st[u].y);
        bv.z = f2tf(b_st[u].z); bv.w = f2tf(b_st[u].w);
        *(uint4*)&Bs[(brow + u * 8) * BP + bcol] = bv;
    }
    __syncthreads();

    float acc[4][4][4];
#pragma unroll
    for (int i = 0; i < 4; i++)
#pragma unroll
        for (int j = 0; j < 4; j++)
#pragma unroll
            for (int c = 0; c < 4; c++) acc[i][j][c] = 0.f;

    const int iters = K / 32;
    for (int it = 0; it < iters; it++) {
        if (it + 1 < iters) {
            const float* Ag2 = Ag + (it + 1) * 32;
            const float* Bg2 = Bg + (size_t)(it + 1) * 32 * N;
#pragma unroll
            for (int u = 0; u < 4; u++) a_st[u] = *(const float4*)(Ag2 + (size_t)(u * 32) * K);
#pragma unroll
            for (int u = 0; u < 4; u++) b_st[u] = *(const float4*)(Bg2 + (size_t)(u * 8) * N);
        }

#pragma unroll
        for (int kk = 0; kk < 4; kk++) {
            const int ks = kk * 8;
            uint32_t af[4][4], bf[4][2];
#pragma unroll
            for (int i = 0; i < 4; i++) {
                const int mr = m0 + i * 16 + g;
                af[i][0] = As[mr * AP + ks + q];
                af[i][1] = As[(mr + 8) * AP + ks + q];
                af[i][2] = As[mr * AP + ks + q + 4];
                af[i][3] = As[(mr + 8) * AP + ks + q + 4];
            }
#pragma unroll
            for (int j = 0; j < 4; j++) {
                const int nc = n0 + j * 8 + g;
                bf[j][0] = Bs[(ks + q) * BP + nc];
                bf[j][1] = Bs[(ks + q + 4) * BP + nc];
            }
#pragma unroll
            for (int i = 0; i < 4; i++)
#pragma unroll
                for (int j = 0; j < 4; j++)
                    mma8(acc[i][j], af[i], bf[j][0], bf[j][1]);
        }

        if (it + 1 < iters) {
            __syncthreads();
#pragma unroll
            for (int u = 0; u < 4; u++) {
                uint4 av;
                av.x = f2tf(a_st[u].x); av.y = f2tf(a_st[u].y);
                av.z = f2tf(a_st[u].z); av.w = f2tf(a_st[u].w);
                *(uint4*)&As[(arow + u * 32) * AP + acol] = av;
                uint4 bv;
                bv.x = f2tf(b_st[u].x); bv.y = f2tf(b_st[u].y);
                bv.z = f2tf(b_st[u].z); bv.w = f2tf(b_st[u].w);
                *(uint4*)&Bs[(brow + u * 8) * BP + bcol] = bv;
            }
            __syncthreads();
        }
    }

#pragma unroll
    for (int i = 0; i < 4; i++) {
#pragma unroll
        for (int j = 0; j < 4; j++) {
            const int row0 = by * 128 + m0 + i * 16 + g;
            const int col = bx * 128 + n0 + j * 8 + 2 * q;
            float v0 = acc[i][j][0], v1 = acc[i][j][1];
            float v2 = acc[i][j][2], v3 = acc[i][j][3];
            if (EPI == 1) {
                float b0v = bias[col], b1v = bias[col + 1];
                v0 += b0v; v1 += b1v; v2 += b0v; v3 += b1v;
                v0 = v0 / (1.f + __expf(-v0));
                v1 = v1 / (1.f + __expf(-v1));
                v2 = v2 / (1.f + __expf(-v2));
                v3 = v3 / (1.f + __expf(-v3));
            }
            if (EPI == 2) {
                v0 = __uint_as_float(f2tf(v0));
                v1 = __uint_as_float(f2tf(v1));
                v2 = __uint_as_float(f2tf(v2));
                v3 = __uint_as_float(f2tf(v3));
            }
            *(float2*)&C[(size_t)row0 * N + col] = make_float2(v0, v1);
            *(float2*)&C[(size_t)(row0 + 8) * N + col] = make_float2(v2, v3);
        }
    }
}

// ------------------- router -------------------
__global__ __launch_bounds__(256) void router_fused_kernel(
    const float* __restrict__ X, const float* __restrict__ Wr2, const float* __restrict__ br2)
{
    const int t = blockIdx.x;
    const int tid = threadIdx.x;
    __shared__ float red[512];
    __shared__ float lam[2];

    float s0 = 0.f, s1 = 0.f;
    for (int j = tid; j < RDIM; j += 256) {
        float hv = g_h[t * RDIM + j];
        s0 = fmaf(hv, Wr2[2 * j + 0], s0);
        s1 = fmaf(hv, Wr2[2 * j + 1], s1);
    }
    red[tid] = s0;
    red[256 + tid] = s1;
    __syncthreads();
    for (int off = 128; off > 0; off >>= 1) {
        if (tid < off) {
            red[tid] += red[tid + off];
            red[256 + tid] += red[256 + tid + off];
        }
        __syncthreads();
    }
    if (tid == 0) {
        float a = red[0] + br2[0];
        float b = red[256] + br2[1];
        float mx = fmaxf(a, b);
        float e0 = __expf(a - mx), e1 = __expf(b - mx);
        float inv = 1.f / (e0 + e1);
        lam[0] = e0 * inv;
        lam[1] = e1 * inv;
    }
    __syncthreads();
    float l0 = lam[0], l1 = lam[1];
    for (int c = tid * 4; c < DD; c += 1024) {
        float4 x4 = *(const float4*)&X[t * DD + c];
        float4 m4 = *(const float4*)&g_l2[t * DD + c];
        float4 o;
        o.x = fmaf(l0, x4.x, l1 * m4.x);
        o.y = fmaf(l0, x4.y, l1 * m4.y);
        o.z = fmaf(l0, x4.z, l1 * m4.z);
        o.w = fmaf(l0, x4.w, l1 * m4.w);
        *(float4*)&g_fused[t * DD + c] = o;
    }
}

// ------------------- RoPE (in place; stores tf32-rounded, optional scale) -------------------
__global__ void rope_kernel(float* __restrict__ M, int rowStride, float scale) {
    int t = blockIdx.x;
    int head = blockIdx.y;
    int i = threadIdx.x;  // 0..63
    double inv = pow(10000.0, -(double)i / 64.0);
    float ang = (float)((double)t * inv);
    float s, c;
    sincosf(ang, &s, &c);
    int base = t * rowStride + head * HDIM;
    float x1 = M[base + i];
    float x2 = M[base + 64 + i];
    float o1 = (x1 * c - x2 * s) * scale;
    float o2 = fmaf(x2, c, x1 * s) * scale;
    M[base + i] = __uint_as_float(f2tf(o1));
    M[base + 64 + i] = __uint_as_float(f2tf(o2));
}

// ------------------- flash attention v2 (causal GQA, tf32 mma, cp.async pipelined) -------------------
// grid (32, 8): 64 q-rows x 2 heads (same KV group) per block. 256 threads (8 warps).
// warp wid: hp = wid>>2 selects head, ws = wid&3 -> rows [16ws, 16ws+16).
// smem: 2 stages x (K 64x132 + V 64x132) tf32 words. Q staged through stage 1 before mainloop.
#define KPAD 132
#define TILE_W (64 * KPAD)                 // 8448 words per K or V buffer
#define ATTN_SMEM_BYTES (4 * TILE_W * 4)   // 135168 B

__global__ __launch_bounds__(256) void attn_kernel() {
    extern __shared__ uint32_t smw[];

    const int qt = (int)gridDim.x - 1 - (int)blockIdx.x;  // heavy blocks first
    const int hp2 = blockIdx.y;
    const int tid = threadIdx.x;
    const int lane = tid & 31;
    const int wid = tid >> 5;
    const int hp = wid >> 2;          // head within pair
    const int ws = wid & 3;           // row-group
    const int h = 2 * hp2 + hp;
    const int kvh = hp2 >> 1;
    const int g = lane >> 2;
    const int q = lane & 3;
    const int m0 = ws * 16;
    const int q0 = qt * 64;

    const uint32_t sb = smem_u32(smw);

    // ---- stage Q of both heads into stage-1 buffers (head0 -> S1K, head1 -> S1V) ----
#pragma unroll
    for (int u = 0; u < 8; u++) {
        int linear = u * 256 + tid;          // 0..2047
        int r = linear >> 5;
        int c4 = (linear & 31) * 4;
        cpasync16(sb + (uint32_t)(2 * TILE_W + r * KPAD + c4) * 4,
                  &g_q[(size_t)(q0 + r) * DQ + (2 * hp2) * HDIM + c4]);
        cpasync16(sb + (uint32_t)(3 * TILE_W + r * KPAD + c4) * 4,
                  &g_q[(size_t)(q0 + r) * DQ + (2 * hp2 + 1) * HDIM + c4]);
    }
    CP_COMMIT();
    CP_WAIT(0);
    __syncthreads();

    uint32_t qf[16][4];
    {
        const uint32_t* Qb = smw + (hp ? 3 * TILE_W : 2 * TILE_W);
#pragma unroll
        for (int kk = 0; kk < 16; kk++) {
            const int base = (m0 + g) * KPAD + kk * 8 + q;
            qf[kk][0] = Qb[base];
            qf[kk][1] = Qb[base + 8 * KPAD];
            qf[kk][2] = Qb[base + 4];
            qf[kk][3] = Qb[base + 8 * KPAD + 4];
        }
    }
    __syncthreads();

    float oacc[16][4];
#pragma unroll
    for (int n = 0; n < 16; n++)
#pragma unroll
        for (int c = 0; c < 4; c++) oacc[n][c] = 0.f;
    float mrow[2] = {-1e30f, -1e30f};
    float lrow[2] = {0.f, 0.f};

    // prefetch tile 0 into stage 0
    {
        const int k0 = 0;
#pragma unroll
        for (int u = 0; u < 8; u++) {
            int linear = u * 256 + tid;
            int r = linear >> 5;
            int c4 = (linear & 31) * 4;
            cpasync16(sb + (uint32_t)(r * KPAD + c4) * 4,
                      &g_k[(size_t)(k0 + r) * DKV + kvh * HDIM + c4]);
            cpasync16(sb + (uint32_t)(TILE_W + r * KPAD + c4) * 4,
                      &g_v[(size_t)(k0 + r) * DKV + kvh * HDIM + c4]);
        }
        CP_COMMIT();
    }

    const int lA = 4 * g + (q >> 1);
    const int lB = lA + 2;
    const bool bq = (q & 1);

    for (int kt = 0; kt <= qt; kt++) {
        const int st = kt & 1;
        if (kt < qt) {
            // prefetch next tile into other stage
            const int k0n = (kt + 1) * 64;
            const uint32_t basew = (uint32_t)((st ^ 1) * 2 * TILE_W);
#pragma unroll
            for (int u = 0; u < 8; u++) {
                int linear = u * 256 + tid;
                int r = linear >> 5;
                int c4 = (linear & 31) * 4;
                cpasync16(sb + (basew + r * KPAD + c4) * 4,
                          &g_k[(size_t)(k0n + r) * DKV + kvh * HDIM + c4]);
                cpasync16(sb + (basew + TILE_W + r * KPAD + c4) * 4,
                          &g_v[(size_t)(k0n + r) * DKV + kvh * HDIM + c4]);
            }
            CP_COMMIT();
            CP_WAIT(1);
        } else {
            CP_WAIT(0);
        }
        __syncthreads();

        const uint32_t* Ksb = smw + st * 2 * TILE_W;
        const uint32_t* Vsb = Ksb + TILE_W;

        // ---- S = Q @ K^T : 16 x 64 per warp ----
        float sacc[8][4];
#pragma unroll
        for (int n = 0; n < 8; n++) {
#pragma unroll
            for (int c = 0; c < 4; c++) sacc[n][c] = 0.f;
            const uint32_t* bb = Ksb + (n * 8 + g) * KPAD + q;
#pragma unroll
            for (int kk = 0; kk < 16; kk++) {
                uint32_t b0 = bb[kk * 8];
                uint32_t b1 = bb[kk * 8 + 4];
                mma8(sacc[n], qf[kk], b0, b1);
            }
        }

        // ---- causal mask (diagonal tile) ----
        if (kt == qt) {
#pragma unroll
            for (int n = 0; n < 8; n++) {
                const int col0 = n * 8 + 2 * q;
                const int rA = m0 + g, rB = m0 + g + 8;
                if (col0 > rA) sacc[n][0] = -1e30f;
                if (col0 + 1 > rA) sacc[n][1] = -1e30f;
                if (col0 > rB) sacc[n][2] = -1e30f;
                if (col0 + 1 > rB) sacc[n][3] = -1e30f;
            }
        }

        // ---- online softmax ----
        float mx0 = -1e30f, mx1 = -1e30f;
#pragma unroll
        for (int n = 0; n < 8; n++) {
            mx0 = fmaxf(mx0, fmaxf(sacc[n][0], sacc[n][1]));
            mx1 = fmaxf(mx1, fmaxf(sacc[n][2], sacc[n][3]));
        }
        mx0 = fmaxf(mx0, __shfl_xor_sync(0xffffffffu, mx0, 1));
        mx0 = fmaxf(mx0, __shfl_xor_sync(0xffffffffu, mx0, 2));
        mx1 = fmaxf(mx1, __shfl_xor_sync(0xffffffffu, mx1, 1));
        mx1 = fmaxf(mx1, __shfl_xor_sync(0xffffffffu, mx1, 2));

        const float nm0 = fmaxf(mrow[0], mx0);
        const float nm1 = fmaxf(mrow[1], mx1);
        const float corr0 = __expf(mrow[0] - nm0);
        const float corr1 = __expf(mrow[1] - nm1);
        float rs0 = 0.f, rs1 = 0.f;
#pragma unroll
        for (int n = 0; n < 8; n++) {
            sacc[n][0] = __expf(sacc[n][0] - nm0);
            sacc[n][1] = __expf(sacc[n][1] - nm0);
            sacc[n][2] = __expf(sacc[n][2] - nm1);
            sacc[n][3] = __expf(sacc[n][3] - nm1);
            rs0 += sacc[n][0] + sacc[n][1];
            rs1 += sacc[n][2] + sacc[n][3];
        }
        rs0 += __shfl_xor_sync(0xffffffffu, rs0, 1);
        rs0 += __shfl_xor_sync(0xffffffffu, rs0, 2);
        rs1 += __shfl_xor_sync(0xffffffffu, rs1, 1);
        rs1 += __shfl_xor_sync(0xffffffffu, rs1, 2);
        lrow[0] = lrow[0] * corr0 + rs0;
        lrow[1] = lrow[1] * corr1 + rs1;
        mrow[0] = nm0;
        mrow[1] = nm1;
#pragma unroll
        for (int n = 0; n < 16; n++) {
            oacc[n][0] *= corr0;
            oacc[n][1] *= corr0;
            oacc[n][2] *= corr1;
            oacc[n][3] *= corr1;
        }

        // ---- P transpose via shfl (C-frag -> A-frag), then O += P @ V ----
#pragma unroll
        for (int kk = 0; kk < 8; kk++) {
            float v0 = __shfl_sync(0xffffffffu, sacc[kk][0], lA);
            float v1 = __shfl_sync(0xffffffffu, sacc[kk][1], lA);
            float v2 = __shfl_sync(0xffffffffu, sacc[kk][2], lA);
            float v3 = __shfl_sync(0xffffffffu, sacc[kk][3], lA);
            float w0 = __shfl_sync(0xffffffffu, sacc[kk][0], lB);
            float w1 = __shfl_sync(0xffffffffu, sacc[kk][1], lB);
            float w2 = __shfl_sync(0xffffffffu, sacc[kk][2], lB);
            float w3 = __shfl_sync(0xffffffffu, sacc[kk][3], lB);
            uint32_t pa[4];
            pa[0] = f2tf(bq ? v1 : v0);
            pa[1] = f2tf(bq ? v3 : v2);
            pa[2] = f2tf(bq ? w1 : w0);
            pa[3] = f2tf(bq ? w3 : w2);
            const uint32_t* vb = Vsb + (kk * 8 + q) * KPAD + g;
#pragma unroll
            for (int n = 0; n < 16; n++) {
                uint32_t b0 = vb[n * 8];
                uint32_t b1 = vb[4 * KPAD + n * 8];
                mma8(oacc[n], pa, b0, b1);
            }
        }
        __syncthreads();
    }

    // ---- write O ----
    const float inv0 = 1.f / lrow[0];
    const float inv1 = 1.f / lrow[1];
    const int rowA = q0 + m0 + g;
    const int rowB = rowA + 8;
#pragma unroll
    for (int n = 0; n < 16; n++) {
        const int col = h * HDIM + n * 8 + 2 * q;
        *(float2*)&g_attn[(size_t)rowA * DQ + col] =
            make_float2(oacc[n][0] * inv0, oacc[n][1] * inv0);
        *(float2*)&g_attn[(size_t)rowB * DQ + col] =
            make_float2(oacc[n][2] * inv1, oacc[n][3] * inv1);
    }
}

// ------------------- host launch -------------------
extern "C" void kernel_launch(void* const* d_in, const int* in_sizes, int n_in,
                              void* d_out, int out_size) {
    const float* X   = (const float*)d_in[0];
    const float* Wq  = (const float*)d_in[1];
    const float* Wk  = (const float*)d_in[2];
    const float* Wv  = (const float*)d_in[3];
    const float* Wo  = (const float*)d_in[4];
    const float* Wr1 = (const float*)d_in[5];
    const float* br1 = (const float*)d_in[6];
    const float* Wr2 = (const float*)d_in[7];
    const float* br2 = (const float*)d_in[8];
    float* out = (float*)d_out;

    float *p_q, *p_h, *p_fused, *p_k, *p_v, *p_attn;
    cudaGetSymbolAddress((void**)&p_q, g_q);
    cudaGetSymbolAddress((void**)&p_h, g_h);
    cudaGetSymbolAddress((void**)&p_fused, g_fused);
    cudaGetSymbolAddress((void**)&p_k, g_k);
    cudaGetSymbolAddress((void**)&p_v, g_v);
    cudaGetSymbolAddress((void**)&p_attn, g_attn);

    cudaFuncSetAttribute(attn_kernel, cudaFuncAttributeMaxDynamicSharedMemorySize, ATTN_SMEM_BYTES);

    // EMA
    ema_local_kernel<<<(EMA_NC * DD) / 256, 256>>>(X);
    ema_scan_kernel<<<DD / 256, 256>>>();
    ema_fix_kernel<<<((EMA_NC - 1) * DD) / 256, 256>>>();

    // q = X @ Wq
    mm_tf32<0><<<dim3(DQ / 128, TT / 128), 256>>>(X, Wq, nullptr, p_q, TT, DQ, DD);
    // h = silu(q @ Wr1 + br1)  (reads pre-RoPE q)
    mm_tf32<1><<<dim3(RDIM / 128, TT / 128), 256>>>(p_q, Wr1, br1, p_h, TT, RDIM, DQ);
    // lam + fused
    router_fused_kernel<<<TT, 256>>>(X, Wr2, br2);
    // k, v (v stored tf32-rounded)
    mm_tf32<0><<<dim3(DKV / 128, TT / 128), 256>>>(p_fused, Wk, nullptr, p_k, TT, DKV, DD);
    mm_tf32<2><<<dim3(DKV / 128, TT / 128), 256>>>(p_fused, Wv, nullptr, p_v, TT, DKV, DD);
    // RoPE: q gets softmax scale folded in + tf32 rounding; k tf32 rounding
    rope_kernel<<<dim3(TT, NH), 64>>>(p_q, DQ, ATTN_SCALE);
    rope_kernel<<<dim3(TT, NKV), 64>>>(p_k, DKV, 1.0f);
    // attention (2 heads per block share KV)
    attn_kernel<<<dim3(TT / 64, NH / 2), 256, ATTN_SMEM_BYTES>>>();
    // out = attn @ Wo
    mm_tf32<0><<<dim3(DD / 128, TT / 128), 256>>>(p_attn, Wo, nullptr, out, TT, DD, DQ);
}

// round 9
// speedup vs baseline: 4.0062x; 1.5102x over previous
#include <cuda_runtime.h>
#include <math.h>
#include <stdint.h>

#define TT 2048
#define DD 2048
#define NH 16
#define NKV 4
#define HDIM 128
#define DQ 2048    // NH*HDIM
#define DKV 512    // NKV*HDIM
#define RDIM 1024  // D/2
#define EMA_L 64
#define EMA_NC 32

#define BETA 0.9f
#define ALPHA 0.1f
#define ATTN_SCALE 0.08838834764831843f  // 1/sqrt(128)
#define LOG2E 1.4426950408889634f

// ------------------- scratch -------------------
__device__ float g_l2[TT * DD];
__device__ float g_q[TT * DQ];
__device__ float g_h[TT * RDIM];
__device__ float g_fused[TT * DD];
__device__ float g_k[TT * DKV];
__device__ float g_v[TT * DKV];
__device__ float g_attn[TT * DQ];
__device__ float g_carry[EMA_NC * DD];
__device__ float g_prefix[EMA_NC * DD];
__device__ double g_invfreq[64];

// ------------------- tf32 / async helpers -------------------
__device__ __forceinline__ uint32_t f2tf(float f) {
    uint32_t u;
    asm("cvt.rna.tf32.f32 %0, %1;" : "=r"(u) : "f"(f));
    return u;
}
__device__ __forceinline__ void mma8(float* c, const uint32_t* a, uint32_t b0, uint32_t b1) {
    asm volatile(
        "mma.sync.aligned.m16n8k8.row.col.f32.tf32.tf32.f32 "
        "{%0,%1,%2,%3}, {%4,%5,%6,%7}, {%8,%9}, {%0,%1,%2,%3};\n"
        : "+f"(c[0]), "+f"(c[1]), "+f"(c[2]), "+f"(c[3])
        : "r"(a[0]), "r"(a[1]), "r"(a[2]), "r"(a[3]), "r"(b0), "r"(b1));
}
__device__ __forceinline__ uint32_t smem_u32(const void* p) {
    uint32_t a;
    asm("{ .reg .u64 t; cvta.to.shared.u64 t, %1; cvt.u32.u64 %0, t; }" : "=r"(a) : "l"(p));
    return a;
}
__device__ __forceinline__ void cpasync16(uint32_t dst, const void* src) {
    asm volatile("cp.async.ca.shared.global [%0], [%1], 16;\n" :: "r"(dst), "l"(src));
}
#define CP_COMMIT() asm volatile("cp.async.commit_group;\n" ::: "memory")
#define CP_WAIT(N) asm volatile("cp.async.wait_group %0;\n" :: "n"(N) : "memory")

// ------------------- RoPE frequency table (64 fp64 pows, once) -------------------
__global__ void freq_kernel() {
    int i = threadIdx.x;  // 0..63
    g_invfreq[i] = pow(10000.0, -(double)i / 64.0);
}

// ------------------- EMA: 3-pass exact chunked scan -------------------
__global__ void ema_local_kernel(const float* __restrict__ X) {
    int g = blockIdx.x * blockDim.x + threadIdx.x;
    int c = g / DD;
    int d = g % DD;
    float m = 0.f;
    int t0 = c * EMA_L;
#pragma unroll 4
    for (int i = 0; i < EMA_L; i++) {
        int t = t0 + i;
        m = fmaf(BETA, m, ALPHA * X[t * DD + d]);
        g_l2[t * DD + d] = m;
    }
    g_carry[c * DD + d] = m;
}

__global__ void ema_scan_kernel() {
    int d = blockIdx.x * blockDim.x + threadIdx.x;
    float bl = 1.f;
#pragma unroll
    for (int i = 0; i < EMA_L; i++) bl *= BETA;
    float m = 0.f;
#pragma unroll
    for (int c = 0; c < EMA_NC; c++) {
        g_prefix[c * DD + d] = m;
        m = fmaf(bl, m, g_carry[c * DD + d]);
    }
}

__global__ void ema_fix_kernel() {
    int g = blockIdx.x * blockDim.x + threadIdx.x;
    int c = g / DD + 1;
    int d = g % DD;
    float p = g_prefix[c * DD + d];
    float f = BETA;
    int t0 = c * EMA_L;
#pragma unroll 4
    for (int i = 0; i < EMA_L; i++) {
        int t = t0 + i;
        g_l2[t * DD + d] = fmaf(f, p, g_l2[t * DD + d]);
        f *= BETA;
    }
}

// ------------------- TF32 GEMM: C = A(MxK) @ B(KxN) row-major -------------------
// block 128x128, BK=32, 256 threads, 8 warps (2m x 4n), warp tile 64x32.
#define AP 36   // A smem pad
#define BP 132  // B smem pad

// EPI: 0 = none, 1 = bias + silu, 2 = store tf32-rounded
template <int EPI>
__global__ __launch_bounds__(256, 2) void mm_tf32(
    const float* __restrict__ A, const float* __restrict__ B,
    const float* __restrict__ bias, float* __restrict__ C,
    int M, int N, int K)
{
    __shared__ uint32_t As[128 * AP];
    __shared__ uint32_t Bs[32 * BP];

    const int tid = threadIdx.x;
    const int bx = blockIdx.x, by = blockIdx.y;

    const int arow = tid >> 3;
    const int acol = (tid & 7) * 4;
    const int brow = tid >> 5;
    const int bcol = (tid & 31) * 4;

    const float* Ag = A + (size_t)(by * 128 + arow) * K + acol;
    const float* Bg = B + (size_t)brow * N + (size_t)bx * 128 + bcol;

    const int lane = tid & 31;
    const int wid = tid >> 5;
    const int wm = wid >> 2;
    const int wn = wid & 3;
    const int m0 = wm * 64;
    const int n0 = wn * 32;
    const int g = lane >> 2;
    const int q = lane & 3;

    float4 a_st[4], b_st[4];
#pragma unroll
    for (int u = 0; u < 4; u++) a_st[u] = *(const float4*)(Ag + (size_t)(u * 32) * K);
#pragma unroll
    for (int u = 0; u < 4; u++) b_st[u] = *(const float4*)(Bg + (size_t)(u * 8) * N);

#pragma unroll
    for (int u = 0; u < 4; u++) {
        uint4 av;
        av.x = f2tf(a_st[u].x); av.y = f2tf(a_st[u].y);
        av.z = f2tf(a_st[u].z); av.w = f2tf(a_st[u].w);
        *(uint4*)&As[(arow + u * 32) * AP + acol] = av;
        uint4 bv;
        bv.x = f2tf(b_st[u].x); bv.y = f2tf(b_st[u].y);
        bv.z = f2tf(b_st[u].z); bv.w = f2tf(b_st[u].w);
        *(uint4*)&Bs[(brow + u * 8) * BP + bcol] = bv;
    }
    __syncthreads();

    float acc[4][4][4];
#pragma unroll
    for (int i = 0; i < 4; i++)
#pragma unroll
        for (int j = 0; j < 4; j++)
#pragma unroll
            for (int c = 0; c < 4; c++) acc[i][j][c] = 0.f;

    const int iters = K / 32;
    for (int it = 0; it < iters; it++) {
        if (it + 1 < iters) {
            const float* Ag2 = Ag + (it + 1) * 32;
            const float* Bg2 = Bg + (size_t)(it + 1) * 32 * N;
#pragma unroll
            for (int u = 0; u < 4; u++) a_st[u] = *(const float4*)(Ag2 + (size_t)(u * 32) * K);
#pragma unroll
            for (int u = 0; u < 4; u++) b_st[u] = *(const float4*)(Bg2 + (size_t)(u * 8) * N);
        }

#pragma unroll
        for (int kk = 0; kk < 4; kk++) {
            const int ks = kk * 8;
            uint32_t af[4][4], bf[4][2];
#pragma unroll
            for (int i = 0; i < 4; i++) {
                const int mr = m0 + i * 16 + g;
                af[i][0] = As[mr * AP + ks + q];
                af[i][1] = As[(mr + 8) * AP + ks + q];
                af[i][2] = As[mr * AP + ks + q + 4];
                af[i][3] = As[(mr + 8) * AP + ks + q + 4];
            }
#pragma unroll
            for (int j = 0; j < 4; j++) {
                const int nc = n0 + j * 8 + g;
                bf[j][0] = Bs[(ks + q) * BP + nc];
                bf[j][1] = Bs[(ks + q + 4) * BP + nc];
            }
#pragma unroll
            for (int i = 0; i < 4; i++)
#pragma unroll
                for (int j = 0; j < 4; j++)
                    mma8(acc[i][j], af[i], bf[j][0], bf[j][1]);
        }

        if (it + 1 < iters) {
            __syncthreads();
#pragma unroll
            for (int u = 0; u < 4; u++) {
                uint4 av;
                av.x = f2tf(a_st[u].x); av.y = f2tf(a_st[u].y);
                av.z = f2tf(a_st[u].z); av.w = f2tf(a_st[u].w);
                *(uint4*)&As[(arow + u * 32) * AP + acol] = av;
                uint4 bv;
                bv.x = f2tf(b_st[u].x); bv.y = f2tf(b_st[u].y);
                bv.z = f2tf(b_st[u].z); bv.w = f2tf(b_st[u].w);
                *(uint4*)&Bs[(brow + u * 8) * BP + bcol] = bv;
            }
            __syncthreads();
        }
    }

#pragma unroll
    for (int i = 0; i < 4; i++) {
#pragma unroll
        for (int j = 0; j < 4; j++) {
            const int row0 = by * 128 + m0 + i * 16 + g;
            const int col = bx * 128 + n0 + j * 8 + 2 * q;
            float v0 = acc[i][j][0], v1 = acc[i][j][1];
            float v2 = acc[i][j][2], v3 = acc[i][j][3];
            if (EPI == 1) {
                float b0v = bias[col], b1v = bias[col + 1];
                v0 += b0v; v1 += b1v; v2 += b0v; v3 += b1v;
                v0 = v0 / (1.f + __expf(-v0));
                v1 = v1 / (1.f + __expf(-v1));
                v2 = v2 / (1.f + __expf(-v2));
                v3 = v3 / (1.f + __expf(-v3));
            }
            if (EPI == 2) {
                v0 = __uint_as_float(f2tf(v0));
                v1 = __uint_as_float(f2tf(v1));
                v2 = __uint_as_float(f2tf(v2));
                v3 = __uint_as_float(f2tf(v3));
            }
            *(float2*)&C[(size_t)row0 * N + col] = make_float2(v0, v1);
            *(float2*)&C[(size_t)(row0 + 8) * N + col] = make_float2(v2, v3);
        }
    }
}

// ------------------- router -------------------
__global__ __launch_bounds__(256) void router_fused_kernel(
    const float* __restrict__ X, const float* __restrict__ Wr2, const float* __restrict__ br2)
{
    const int t = blockIdx.x;
    const int tid = threadIdx.x;
    __shared__ float red[512];
    __shared__ float lam[2];

    float s0 = 0.f, s1 = 0.f;
    for (int j = tid; j < RDIM; j += 256) {
        float hv = g_h[t * RDIM + j];
        s0 = fmaf(hv, Wr2[2 * j + 0], s0);
        s1 = fmaf(hv, Wr2[2 * j + 1], s1);
    }
    red[tid] = s0;
    red[256 + tid] = s1;
    __syncthreads();
    for (int off = 128; off > 0; off >>= 1) {
        if (tid < off) {
            red[tid] += red[tid + off];
            red[256 + tid] += red[256 + tid + off];
        }
        __syncthreads();
    }
    if (tid == 0) {
        float a = red[0] + br2[0];
        float b = red[256] + br2[1];
        float mx = fmaxf(a, b);
        float e0 = __expf(a - mx), e1 = __expf(b - mx);
        float inv = 1.f / (e0 + e1);
        lam[0] = e0 * inv;
        lam[1] = e1 * inv;
    }
    __syncthreads();
    float l0 = lam[0], l1 = lam[1];
    for (int c = tid * 4; c < DD; c += 1024) {
        float4 x4 = *(const float4*)&X[t * DD + c];
        float4 m4 = *(const float4*)&g_l2[t * DD + c];
        float4 o;
        o.x = fmaf(l0, x4.x, l1 * m4.x);
        o.y = fmaf(l0, x4.y, l1 * m4.y);
        o.z = fmaf(l0, x4.z, l1 * m4.z);
        o.w = fmaf(l0, x4.w, l1 * m4.w);
        *(float4*)&g_fused[t * DD + c] = o;
    }
}

// ------------------- RoPE (table-driven; in place; stores tf32-rounded, optional scale) ----
// grid: (TT). block: 256 threads = 4 (head-slots) x 64 (rot index).
__global__ __launch_bounds__(256) void rope_kernel(float* __restrict__ M, int rowStride,
                                                   int nheads, float scale) {
    const int t = blockIdx.x;
    const int tid = threadIdx.x;
    const int hh = tid >> 6;   // 0..3
    const int i = tid & 63;    // 0..63
    const double inv = g_invfreq[i];
    const float ang = (float)((double)t * inv);
    float s, c;
    sincosf(ang, &s, &c);
    for (int head = hh; head < nheads; head += 4) {
        const int base = t * rowStride + head * HDIM;
        float x1 = M[base + i];
        float x2 = M[base + 64 + i];
        float o1 = (x1 * c - x2 * s) * scale;
        float o2 = fmaf(x2, c, x1 * s) * scale;
        M[base + i] = __uint_as_float(f2tf(o1));
        M[base + 64 + i] = __uint_as_float(f2tf(o2));
    }
}

// ------------------- flash attention (causal GQA, tf32 mma, cp.async pipelined, exp2) ------
// grid (32, 8): 64 q-rows x 2 heads (same KV group) per block. 256 threads (8 warps).
#define KPAD 132
#define TILE_W (64 * KPAD)                 // 8448 words per K or V buffer
#define ATTN_SMEM_BYTES (4 * TILE_W * 4)   // 135168 B

__global__ __launch_bounds__(256) void attn_kernel() {
    extern __shared__ uint32_t smw[];

    const int qt = (int)gridDim.x - 1 - (int)blockIdx.x;  // heavy blocks first
    const int hp2 = blockIdx.y;
    const int tid = threadIdx.x;
    const int lane = tid & 31;
    const int wid = tid >> 5;
    const int hp = wid >> 2;          // head within pair
    const int ws = wid & 3;           // row-group
    const int h = 2 * hp2 + hp;
    const int kvh = hp2 >> 1;
    const int g = lane >> 2;
    const int q = lane & 3;
    const int m0 = ws * 16;
    const int q0 = qt * 64;

    const uint32_t sb = smem_u32(smw);

    // ---- stage Q of both heads into stage-1 buffers ----
#pragma unroll
    for (int u = 0; u < 8; u++) {
        int linear = u * 256 + tid;
        int r = linear >> 5;
        int c4 = (linear & 31) * 4;
        cpasync16(sb + (uint32_t)(2 * TILE_W + r * KPAD + c4) * 4,
                  &g_q[(size_t)(q0 + r) * DQ + (2 * hp2) * HDIM + c4]);
        cpasync16(sb + (uint32_t)(3 * TILE_W + r * KPAD + c4) * 4,
                  &g_q[(size_t)(q0 + r) * DQ + (2 * hp2 + 1) * HDIM + c4]);
    }
    CP_COMMIT();
    CP_WAIT(0);
    __syncthreads();

    uint32_t qf[16][4];
    {
        const uint32_t* Qb = smw + (hp ? 3 * TILE_W : 2 * TILE_W);
#pragma unroll
        for (int kk = 0; kk < 16; kk++) {
            const int base = (m0 + g) * KPAD + kk * 8 + q;
            qf[kk][0] = Qb[base];
            qf[kk][1] = Qb[base + 8 * KPAD];
            qf[kk][2] = Qb[base + 4];
            qf[kk][3] = Qb[base + 8 * KPAD + 4];
        }
    }
    __syncthreads();

    float oacc[16][4];
#pragma unroll
    for (int n = 0; n < 16; n++)
#pragma unroll
        for (int c = 0; c < 4; c++) oacc[n][c] = 0.f;
    float mrow[2] = {-1e30f, -1e30f};
    float lrow[2] = {0.f, 0.f};

    // prefetch tile 0 into stage 0
    {
#pragma unroll
        for (int u = 0; u < 8; u++) {
            int linear = u * 256 + tid;
            int r = linear >> 5;
            int c4 = (linear & 31) * 4;
            cpasync16(sb + (uint32_t)(r * KPAD + c4) * 4,
                      &g_k[(size_t)r * DKV + kvh * HDIM + c4]);
            cpasync16(sb + (uint32_t)(TILE_W + r * KPAD + c4) * 4,
                      &g_v[(size_t)r * DKV + kvh * HDIM + c4]);
        }
        CP_COMMIT();
    }

    const int lA = 4 * g + (q >> 1);
    const int lB = lA + 2;
    const bool bq = (q & 1);

    for (int kt = 0; kt <= qt; kt++) {
        const int st = kt & 1;
        if (kt < qt) {
            const int k0n = (kt + 1) * 64;
            const uint32_t basew = (uint32_t)((st ^ 1) * 2 * TILE_W);
#pragma unroll
            for (int u = 0; u < 8; u++) {
                int linear = u * 256 + tid;
                int r = linear >> 5;
                int c4 = (linear & 31) * 4;
                cpasync16(sb + (basew + r * KPAD + c4) * 4,
                          &g_k[(size_t)(k0n + r) * DKV + kvh * HDIM + c4]);
                cpasync16(sb + (basew + TILE_W + r * KPAD + c4) * 4,
                          &g_v[(size_t)(k0n + r) * DKV + kvh * HDIM + c4]);
            }
            CP_COMMIT();
            CP_WAIT(1);
        } else {
            CP_WAIT(0);
        }
        __syncthreads();

        const uint32_t* Ksb = smw + st * 2 * TILE_W;
        const uint32_t* Vsb = Ksb + TILE_W;

        // ---- S = Q @ K^T : 16 x 64 per warp (log2e domain via Q scale) ----
        float sacc[8][4];
#pragma unroll
        for (int n = 0; n < 8; n++) {
#pragma unroll
            for (int c = 0; c < 4; c++) sacc[n][c] = 0.f;
            const uint32_t* bb = Ksb + (n * 8 + g) * KPAD + q;
#pragma unroll
            for (int kk = 0; kk < 16; kk++) {
                uint32_t b0 = bb[kk * 8];
                uint32_t b1 = bb[kk * 8 + 4];
                mma8(sacc[n], qf[kk], b0, b1);
            }
        }

        // ---- causal mask (diagonal tile) ----
        if (kt == qt) {
#pragma unroll
            for (int n = 0; n < 8; n++) {
                const int col0 = n * 8 + 2 * q;
                const int rA = m0 + g, rB = m0 + g + 8;
                if (col0 > rA) sacc[n][0] = -1e30f;
                if (col0 + 1 > rA) sacc[n][1] = -1e30f;
                if (col0 > rB) sacc[n][2] = -1e30f;
                if (col0 + 1 > rB) sacc[n][3] = -1e30f;
            }
        }

        // ---- online softmax (base-2) ----
        float mx0 = -1e30f, mx1 = -1e30f;
#pragma unroll
        for (int n = 0; n < 8; n++) {
            mx0 = fmaxf(mx0, fmaxf(sacc[n][0], sacc[n][1]));
            mx1 = fmaxf(mx1, fmaxf(sacc[n][2], sacc[n][3]));
        }
        mx0 = fmaxf(mx0, __shfl_xor_sync(0xffffffffu, mx0, 1));
        mx0 = fmaxf(mx0, __shfl_xor_sync(0xffffffffu, mx0, 2));
        mx1 = fmaxf(mx1, __shfl_xor_sync(0xffffffffu, mx1, 1));
        mx1 = fmaxf(mx1, __shfl_xor_sync(0xffffffffu, mx1, 2));

        const float nm0 = fmaxf(mrow[0], mx0);
        const float nm1 = fmaxf(mrow[1], mx1);
        const float corr0 = exp2f(mrow[0] - nm0);
        const float corr1 = exp2f(mrow[1] - nm1);
        float rs0 = 0.f, rs1 = 0.f;
#pragma unroll
        for (int n = 0; n < 8; n++) {
            sacc[n][0] = exp2f(sacc[n][0] - nm0);
            sacc[n][1] = exp2f(sacc[n][1] - nm0);
            sacc[n][2] = exp2f(sacc[n][2] - nm1);
            sacc[n][3] = exp2f(sacc[n][3] - nm1);
            rs0 += sacc[n][0] + sacc[n][1];
            rs1 += sacc[n][2] + sacc[n][3];
        }
        rs0 += __shfl_xor_sync(0xffffffffu, rs0, 1);
        rs0 += __shfl_xor_sync(0xffffffffu, rs0, 2);
        rs1 += __shfl_xor_sync(0xffffffffu, rs1, 1);
        rs1 += __shfl_xor_sync(0xffffffffu, rs1, 2);
        lrow[0] = lrow[0] * corr0 + rs0;
        lrow[1] = lrow[1] * corr1 + rs1;
        mrow[0] = nm0;
        mrow[1] = nm1;
#pragma unroll
        for (int n = 0; n < 16; n++) {
            oacc[n][0] *= corr0;
            oacc[n][1] *= corr0;
            oacc[n][2] *= corr1;
            oacc[n][3] *= corr1;
        }

        // ---- P transpose via shfl (C-frag -> A-frag), then O += P @ V ----
#pragma unroll
        for (int kk = 0; kk < 8; kk++) {
            float v0 = __shfl_sync(0xffffffffu, sacc[kk][0], lA);
            float v1 = __shfl_sync(0xffffffffu, sacc[kk][1], lA);
            float v2 = __shfl_sync(0xffffffffu, sacc[kk][2], lA);
            float v3 = __shfl_sync(0xffffffffu, sacc[kk][3], lA);
            float w0 = __shfl_sync(0xffffffffu, sacc[kk][0], lB);
            float w1 = __shfl_sync(0xffffffffu, sacc[kk][1], lB);
            float w2 = __shfl_sync(0xffffffffu, sacc[kk][2], lB);
            float w3 = __shfl_sync(0xffffffffu, sacc[kk][3], lB);
            uint32_t pa[4];
            pa[0] = f2tf(bq ? v1 : v0);
            pa[1] = f2tf(bq ? v3 : v2);
            pa[2] = f2tf(bq ? w1 : w0);
            pa[3] = f2tf(bq ? w3 : w2);
            const uint32_t* vb = Vsb + (kk * 8 + q) * KPAD + g;
#pragma unroll
            for (int n = 0; n < 16; n++) {
                uint32_t b0 = vb[n * 8];
                uint32_t b1 = vb[4 * KPAD + n * 8];
                mma8(oacc[n], pa, b0, b1);
            }
        }
        __syncthreads();
    }

    // ---- write O ----
    const float inv0 = 1.f / lrow[0];
    const float inv1 = 1.f / lrow[1];
    const int rowA = q0 + m0 + g;
    const int rowB = rowA + 8;
#pragma unroll
    for (int n = 0; n < 16; n++) {
        const int col = h * HDIM + n * 8 + 2 * q;
        *(float2*)&g_attn[(size_t)rowA * DQ + col] =
            make_float2(oacc[n][0] * inv0, oacc[n][1] * inv0);
        *(float2*)&g_attn[(size_t)rowB * DQ + col] =
            make_float2(oacc[n][2] * inv1, oacc[n][3] * inv1);
    }
}

// ------------------- host launch -------------------
extern "C" void kernel_launch(void* const* d_in, const int* in_sizes, int n_in,
                              void* d_out, int out_size) {
    const float* X   = (const float*)d_in[0];
    const float* Wq  = (const float*)d_in[1];
    const float* Wk  = (const float*)d_in[2];
    const float* Wv  = (const float*)d_in[3];
    const float* Wo  = (const float*)d_in[4];
    const float* Wr1 = (const float*)d_in[5];
    const float* br1 = (const float*)d_in[6];
    const float* Wr2 = (const float*)d_in[7];
    const float* br2 = (const float*)d_in[8];
    float* out = (float*)d_out;

    float *p_q, *p_h, *p_fused, *p_k, *p_v, *p_attn;
    cudaGetSymbolAddress((void**)&p_q, g_q);
    cudaGetSymbolAddress((void**)&p_h, g_h);
    cudaGetSymbolAddress((void**)&p_fused, g_fused);
    cudaGetSymbolAddress((void**)&p_k, g_k);
    cudaGetSymbolAddress((void**)&p_v, g_v);
    cudaGetSymbolAddress((void**)&p_attn, g_attn);

    cudaFuncSetAttribute(attn_kernel, cudaFuncAttributeMaxDynamicSharedMemorySize, ATTN_SMEM_BYTES);

    // RoPE freq table (64 fp64 pows, one tiny block)
    freq_kernel<<<1, 64>>>();

    // EMA
    ema_local_kernel<<<(EMA_NC * DD) / 256, 256>>>(X);
    ema_scan_kernel<<<DD / 256, 256>>>();
    ema_fix_kernel<<<((EMA_NC - 1) * DD) / 256, 256>>>();

    // q = X @ Wq
    mm_tf32<0><<<dim3(DQ / 128, TT / 128), 256>>>(X, Wq, nullptr, p_q, TT, DQ, DD);
    // h = silu(q @ Wr1 + br1)  (reads pre-RoPE q)
    mm_tf32<1><<<dim3(RDIM / 128, TT / 128), 256>>>(p_q, Wr1, br1, p_h, TT, RDIM, DQ);
    // lam + fused
    router_fused_kernel<<<TT, 256>>>(X, Wr2, br2);
    // k, v (v stored tf32-rounded)
    mm_tf32<0><<<dim3(DKV / 128, TT / 128), 256>>>(p_fused, Wk, nullptr, p_k, TT, DKV, DD);
    mm_tf32<2><<<dim3(DKV / 128, TT / 128), 256>>>(p_fused, Wv, nullptr, p_v, TT, DKV, DD);
    // RoPE: q gets softmax scale * log2e folded in; k plain; both tf32-rounded
    rope_kernel<<<TT, 256>>>(p_q, DQ, NH, ATTN_SCALE * LOG2E);
    rope_kernel<<<TT, 256>>>(p_k, DKV, NKV, 1.0f);
    // attention (2 heads per block share KV; exp2 softmax)
    attn_kernel<<<dim3(TT / 64, NH / 2), 256, ATTN_SMEM_BYTES>>>();
    // out = attn @ Wo
    mm_tf32<0><<<dim3(DD / 128, TT / 128), 256>>>(p_attn, Wo, nullptr, out, TT, DD, DQ);
}

// round 10
// speedup vs baseline: 4.3696x; 1.0907x over previous
#include <cuda_runtime.h>
#include <math.h>
#include <stdint.h>

#define TT 2048
#define DD 2048
#define NH 16
#define NKV 4
#define HDIM 128
#define DQ 2048    // NH*HD
#define DKV 512    // NKV*HD
#define RDIM 1024  // D/2
#define EMA_L 64
#define EMA_NC 32

#define BETA 0.9f
#define ALPHA 0.1f
#define ATTN_SCALE 0.08838834764831843f  // 1/sqrt(128)
#define LOG2E 1.4426950408889634f

// ------------------- scratch -------------------
__device__ float g_l2[TT * DD];
__device__ float g_q[TT * DQ];
__device__ float g_h[TT * RDIM];
__device__ float g_fused[TT * DD];
__device__ float g_k[TT * DKV];
__device__ float g_v[TT * DKV];
__device__ float g_attn[TT * DQ];
__device__ float g_carry[EMA_NC * DD];
__device__ float g_prefix[EMA_NC * DD];
__device__ double g_invfreq[64];
// tf32-pre-rounded operand copies
__device__ float g_xr[TT * DD];
__device__ float g_wq[DD * DQ];
__device__ float g_wk[DD * DKV];
__device__ float g_wv[DD * DKV];
__device__ float g_wo[DQ * DD];
__device__ float g_wr1[DD * RDIM];

// ------------------- tf32 / async helpers -------------------
__device__ __forceinline__ uint32_t f2tf(float f) {
    uint32_t u;
    asm("cvt.rna.tf32.f32 %0, %1;" : "=r"(u) : "f"(f));
    return u;
}
__device__ __forceinline__ void mma8(float* c, const uint32_t* a, uint32_t b0, uint32_t b1) {
    asm volatile(
        "mma.sync.aligned.m16n8k8.row.col.f32.tf32.tf32.f32 "
        "{%0,%1,%2,%3}, {%4,%5,%6,%7}, {%8,%9}, {%0,%1,%2,%3};\n"
        : "+f"(c[0]), "+f"(c[1]), "+f"(c[2]), "+f"(c[3])
        : "r"(a[0]), "r"(a[1]), "r"(a[2]), "r"(a[3]), "r"(b0), "r"(b1));
}
__device__ __forceinline__ uint32_t smem_u32(const void* p) {
    uint32_t a;
    asm("{ .reg .u64 t; cvta.to.shared.u64 t, %1; cvt.u32.u64 %0, t; }" : "=r"(a) : "l"(p));
    return a;
}
__device__ __forceinline__ void cpasync16(uint32_t dst, const void* src) {
    asm volatile("cp.async.ca.shared.global [%0], [%1], 16;\n" :: "r"(dst), "l"(src));
}
#define CP_COMMIT() asm volatile("cp.async.commit_group;\n" ::: "memory")
#define CP_WAIT(N) asm volatile("cp.async.wait_group %0;\n" :: "n"(N) : "memory")

// ------------------- RoPE frequency table -------------------
__global__ void freq_kernel() {
    int i = threadIdx.x;
    g_invfreq[i] = pow(10000.0, -(double)i / 64.0);
}

// ------------------- weight tf32 pre-round (float4 streaming) -------------------
__global__ __launch_bounds__(256) void round4_kernel(const float* __restrict__ in,
                                                     float* __restrict__ out) {
    int i = (blockIdx.x * 256 + threadIdx.x) * 4;
    float4 v = *(const float4*)&in[i];
    float4 o;
    o.x = __uint_as_float(f2tf(v.x));
    o.y = __uint_as_float(f2tf(v.y));
    o.z = __uint_as_float(f2tf(v.z));
    o.w = __uint_as_float(f2tf(v.w));
    *(float4*)&out[i] = o;
}

// ------------------- EMA: 3-pass exact chunked scan (float4) -------------------
// also produces g_xr = tf32-rounded X
__global__ __launch_bounds__(256) void ema_local_kernel(const float* __restrict__ X) {
    int gidx = blockIdx.x * 256 + threadIdx.x;   // 0 .. EMA_NC*512-1
    int c = gidx >> 9;
    int d4 = (gidx & 511) << 2;
    float4 m = make_float4(0.f, 0.f, 0.f, 0.f);
    int t0 = c * EMA_L;
#pragma unroll 2
    for (int i = 0; i < EMA_L; i++) {
        size_t off = (size_t)(t0 + i) * DD + d4;
        float4 x = *(const float4*)&X[off];
        m.x = fmaf(BETA, m.x, ALPHA * x.x);
        m.y = fmaf(BETA, m.y, ALPHA * x.y);
        m.z = fmaf(BETA, m.z, ALPHA * x.z);
        m.w = fmaf(BETA, m.w, ALPHA * x.w);
        *(float4*)&g_l2[off] = m;
        float4 xr;
        xr.x = __uint_as_float(f2tf(x.x));
        xr.y = __uint_as_float(f2tf(x.y));
        xr.z = __uint_as_float(f2tf(x.z));
        xr.w = __uint_as_float(f2tf(x.w));
        *(float4*)&g_xr[off] = xr;
    }
    *(float4*)&g_carry[c * DD + d4] = m;
}

__global__ void ema_scan_kernel() {
    int d4 = (blockIdx.x * 256 + threadIdx.x) * 4;  // 512 threads
    float bl = 1.f;
#pragma unroll
    for (int i = 0; i < EMA_L; i++) bl *= BETA;
    float4 m = make_float4(0.f, 0.f, 0.f, 0.f);
#pragma unroll
    for (int c = 0; c < EMA_NC; c++) {
        *(float4*)&g_prefix[c * DD + d4] = m;
        float4 cr = *(const float4*)&g_carry[c * DD + d4];
        m.x = fmaf(bl, m.x, cr.x);
        m.y = fmaf(bl, m.y, cr.y);
        m.z = fmaf(bl, m.z, cr.z);
        m.w = fmaf(bl, m.w, cr.w);
    }
}

__global__ __launch_bounds__(256) void ema_fix_kernel() {
    int gidx = blockIdx.x * 256 + threadIdx.x;   // 0 .. (EMA_NC-1)*512-1
    int c = (gidx >> 9) + 1;
    int d4 = (gidx & 511) << 2;
    float4 p = *(const float4*)&g_prefix[c * DD + d4];
    float f = BETA;
    int t0 = c * EMA_L;
#pragma unroll 2
    for (int i = 0; i < EMA_L; i++) {
        size_t off = (size_t)(t0 + i) * DD + d4;
        float4 v = *(float4*)&g_l2[off];
        v.x = fmaf(f, p.x, v.x);
        v.y = fmaf(f, p.y, v.y);
        v.z = fmaf(f, p.z, v.z);
        v.w = fmaf(f, p.w, v.w);
        *(float4*)&g_l2[off] = v;
        f *= BETA;
    }
}

// ------------------- TF32 GEMM v3: 3-stage cp.async pipeline -------------------
// block 128x128, BK=32, 256 threads, 8 warps (2m x 4n), warp tile 64x32.
// ALL inputs must be tf32-pre-rounded in gmem.
#define AP 36
#define BP 132
#define ASZ (128 * AP)          // 4608 words
#define BSZ (32 * BP)           // 4224 words
#define STGW (ASZ + BSZ)        // 8832 words per stage
#define MM_SMEM_BYTES (3 * STGW * 4)  // 105984 B

__device__ __forceinline__ void mm_issue(uint32_t sbase, const float* Ax, const float* Bx,
                                         const uint32_t* aOffs, const uint32_t* bOffs,
                                         int N, int K) {
#pragma unroll
    for (int u = 0; u < 4; u++) cpasync16(sbase + aOffs[u], Ax + (size_t)(32 * u) * K);
#pragma unroll
    for (int u = 0; u < 4; u++) cpasync16(sbase + bOffs[u], Bx + (size_t)(8 * u) * N);
    CP_COMMIT();
}

// EPI: 0 = none, 1 = bias + silu, 2 = store tf32-rounded
template <int EPI>
__device__ __forceinline__ void mm_core(
    const float* __restrict__ A, const float* __restrict__ B,
    const float* __restrict__ bias, float* __restrict__ C,
    int N, int K, int bx, int by, uint32_t* sm)
{
    const int tid = threadIdx.x;
    const int aRow = tid >> 3;
    const int aCol = (tid & 7) * 4;
    const int bRow = tid >> 5;
    const int bCol = (tid & 31) * 4;

    const float* Asrc = A + (size_t)(by * 128 + aRow) * K + aCol;
    const float* Bsrc = B + (size_t)bRow * N + bx * 128 + bCol;

    const uint32_t sb = smem_u32(sm);
    uint32_t aOffs[4], bOffs[4];
#pragma unroll
    for (int u = 0; u < 4; u++) {
        aOffs[u] = (uint32_t)(((aRow + 32 * u) * AP + aCol) * 4);
        bOffs[u] = (uint32_t)((ASZ + (bRow + 8 * u) * BP + bCol) * 4);
    }

    const int lane = tid & 31;
    const int wid = tid >> 5;
    const int m0 = (wid >> 2) * 64;
    const int n0 = (wid & 3) * 32;
    const int g = lane >> 2;
    const int q = lane & 3;

    const int iters = K / 32;
    // prologue: tiles 0,1 into slots 0,1
    mm_issue(sb, Asrc, Bsrc, aOffs, bOffs, N, K);
    mm_issue(sb + STGW * 4, Asrc + 32, Bsrc + (size_t)32 * N, aOffs, bOffs, N, K);

    float acc[4][4][4];
#pragma unroll
    for (int i = 0; i < 4; i++)
#pragma unroll
        for (int j = 0; j < 4; j++)
#pragma unroll
            for (int c = 0; c < 4; c++) acc[i][j][c] = 0.f;

    for (int it = 0; it < iters; it++) {
        CP_WAIT(1);
        __syncthreads();

        const int nt = it + 2;
        if (nt < iters) {
            mm_issue(sb + (uint32_t)((nt % 3) * STGW * 4),
                     Asrc + (size_t)nt * 32, Bsrc + (size_t)nt * 32 * N,
                     aOffs, bOffs, N, K);
        } else {
            CP_COMMIT();  // keep group accounting uniform
        }

        const uint32_t* As = sm + (it % 3) * STGW;
        const uint32_t* Bs = As + ASZ;

#pragma unroll
        for (int kk = 0; kk < 4; kk++) {
            const int ks = kk * 8;
            uint32_t af[4][4], bf[4][2];
#pragma unroll
            for (int i = 0; i < 4; i++) {
                const int mr = m0 + i * 16 + g;
                af[i][0] = As[mr * AP + ks + q];
                af[i][1] = As[(mr + 8) * AP + ks + q];
                af[i][2] = As[mr * AP + ks + q + 4];
                af[i][3] = As[(mr + 8) * AP + ks + q + 4];
            }
#pragma unroll
            for (int j = 0; j < 4; j++) {
                const int nc = n0 + j * 8 + g;
                bf[j][0] = Bs[(ks + q) * BP + nc];
                bf[j][1] = Bs[(ks + q + 4) * BP + nc];
            }
#pragma unroll
            for (int i = 0; i < 4; i++)
#pragma unroll
                for (int j = 0; j < 4; j++)
                    mma8(acc[i][j], af[i], bf[j][0], bf[j][1]);
        }
    }

#pragma unroll
    for (int i = 0; i < 4; i++) {
#pragma unroll
        for (int j = 0; j < 4; j++) {
            const int row0 = by * 128 + m0 + i * 16 + g;
            const int col = bx * 128 + n0 + j * 8 + 2 * q;
            float v0 = acc[i][j][0], v1 = acc[i][j][1];
            float v2 = acc[i][j][2], v3 = acc[i][j][3];
            if (EPI == 1) {
                float b0v = bias[col], b1v = bias[col + 1];
                v0 += b0v; v1 += b1v; v2 += b0v; v3 += b1v;
                v0 = v0 / (1.f + __expf(-v0));
                v1 = v1 / (1.f + __expf(-v1));
                v2 = v2 / (1.f + __expf(-v2));
                v3 = v3 / (1.f + __expf(-v3));
            }
            if (EPI == 2) {
                v0 = __uint_as_float(f2tf(v0));
                v1 = __uint_as_float(f2tf(v1));
                v2 = __uint_as_float(f2tf(v2));
                v3 = __uint_as_float(f2tf(v3));
            }
            *(float2*)&C[(size_t)row0 * N + col] = make_float2(v0, v1);
            *(float2*)&C[(size_t)(row0 + 8) * N + col] = make_float2(v2, v3);
        }
    }
}

template <int EPI>
__global__ __launch_bounds__(256, 2) void mm3(
    const float* __restrict__ A, const float* __restrict__ B,
    const float* __restrict__ bias, float* __restrict__ C, int N, int K)
{
    extern __shared__ uint32_t sm[];
    mm_core<EPI>(A, B, bias, C, N, K, blockIdx.x, blockIdx.y, sm);
}

// fused K/V projection: grid.x in [0,8): first 4 -> Wk/C0, last 4 -> Wv/C1. EPI=2 both.
__global__ __launch_bounds__(256, 2) void mm3_kv(
    const float* __restrict__ A,
    const float* __restrict__ B0, const float* __restrict__ B1,
    float* __restrict__ C0, float* __restrict__ C1, int K)
{
    extern __shared__ uint32_t sm[];
    const int sel = blockIdx.x >> 2;
    mm_core<2>(A, sel ? B1 : B0, nullptr, sel ? C1 : C0,
               DKV, K, blockIdx.x & 3, blockIdx.y, sm);
}

// ------------------- router (stores tf32-rounded fused) -------------------
__global__ __launch_bounds__(256) void router_fused_kernel(
    const float* __restrict__ X, const float* __restrict__ Wr2, const float* __restrict__ br2)
{
    const int t = blockIdx.x;
    const int tid = threadIdx.x;
    __shared__ float red[512];
    __shared__ float lam[2];

    float s0 = 0.f, s1 = 0.f;
    for (int j = tid; j < RDIM; j += 256) {
        float hv = g_h[t * RDIM + j];
        s0 = fmaf(hv, Wr2[2 * j + 0], s0);
        s1 = fmaf(hv, Wr2[2 * j + 1], s1);
    }
    red[tid] = s0;
    red[256 + tid] = s1;
    __syncthreads();
    for (int off = 128; off > 0; off >>= 1) {
        if (tid < off) {
            red[tid] += red[tid + off];
            red[256 + tid] += red[256 + tid + off];
        }
        __syncthreads();
    }
    if (tid == 0) {
        float a = red[0] + br2[0];
        float b = red[256] + br2[1];
        float mx = fmaxf(a, b);
        float e0 = __expf(a - mx), e1 = __expf(b - mx);
        float inv = 1.f / (e0 + e1);
        lam[0] = e0 * inv;
        lam[1] = e1 * inv;
    }
    __syncthreads();
    float l0 = lam[0], l1 = lam[1];
    for (int c = tid * 4; c < DD; c += 1024) {
        float4 x4 = *(const float4*)&X[t * DD + c];
        float4 m4 = *(const float4*)&g_l2[t * DD + c];
        float4 o;
        o.x = __uint_as_float(f2tf(fmaf(l0, x4.x, l1 * m4.x)));
        o.y = __uint_as_float(f2tf(fmaf(l0, x4.y, l1 * m4.y)));
        o.z = __uint_as_float(f2tf(fmaf(l0, x4.z, l1 * m4.z)));
        o.w = __uint_as_float(f2tf(fmaf(l0, x4.w, l1 * m4.w)));
        *(float4*)&g_fused[t * DD + c] = o;
    }
}

// ------------------- RoPE (table-driven; stores tf32-rounded, optional scale) ----
__global__ __launch_bounds__(256) void rope_kernel(float* __restrict__ M, int rowStride,
                                                   int nheads, float scale) {
    const int t = blockIdx.x;
    const int tid = threadIdx.x;
    const int hh = tid >> 6;
    const int i = tid & 63;
    const double inv = g_invfreq[i];
    const float ang = (float)((double)t * inv);
    float s, c;
    sincosf(ang, &s, &c);
    for (int head = hh; head < nheads; head += 4) {
        const int base = t * rowStride + head * HDIM;
        float x1 = M[base + i];
        float x2 = M[base + 64 + i];
        float o1 = (x1 * c - x2 * s) * scale;
        float o2 = fmaf(x2, c, x1 * s) * scale;
        M[base + i] = __uint_as_float(f2tf(o1));
        M[base + 64 + i] = __uint_as_float(f2tf(o2));
    }
}

// ------------------- flash attention (causal GQA, tf32 mma, cp.async, exp2) ------
#define KPAD 132
#define TILE_W (64 * KPAD)
#define ATTN_SMEM_BYTES (4 * TILE_W * 4)

__global__ __launch_bounds__(256) void attn_kernel() {
    extern __shared__ uint32_t smw[];

    const int qt = (int)gridDim.x - 1 - (int)blockIdx.x;
    const int hp2 = blockIdx.y;
    const int tid = threadIdx.x;
    const int lane = tid & 31;
    const int wid = tid >> 5;
    const int hp = wid >> 2;
    const int ws = wid & 3;
    const int h = 2 * hp2 + hp;
    const int kvh = hp2 >> 1;
    const int g = lane >> 2;
    const int q = lane & 3;
    const int m0 = ws * 16;
    const int q0 = qt * 64;

    const uint32_t sb = smem_u32(smw);

#pragma unroll
    for (int u = 0; u < 8; u++) {
        int linear = u * 256 + tid;
        int r = linear >> 5;
        int c4 = (linear & 31) * 4;
        cpasync16(sb + (uint32_t)(2 * TILE_W + r * KPAD + c4) * 4,
                  &g_q[(size_t)(q0 + r) * DQ + (2 * hp2) * HDIM + c4]);
        cpasync16(sb + (uint32_t)(3 * TILE_W + r * KPAD + c4) * 4,
                  &g_q[(size_t)(q0 + r) * DQ + (2 * hp2 + 1) * HDIM + c4]);
    }
    CP_COMMIT();
    CP_WAIT(0);
    __syncthreads();

    uint32_t qf[16][4];
    {
        const uint32_t* Qb = smw + (hp ? 3 * TILE_W : 2 * TILE_W);
#pragma unroll
        for (int kk = 0; kk < 16; kk++) {
            const int base = (m0 + g) * KPAD + kk * 8 + q;
            qf[kk][0] = Qb[base];
            qf[kk][1] = Qb[base + 8 * KPAD];
            qf[kk][2] = Qb[base + 4];
            qf[kk][3] = Qb[base + 8 * KPAD + 4];
        }
    }
    __syncthreads();

    float oacc[16][4];
#pragma unroll
    for (int n = 0; n < 16; n++)
#pragma unroll
        for (int c = 0; c < 4; c++) oacc[n][c] = 0.f;
    float mrow[2] = {-1e30f, -1e30f};
    float lrow[2] = {0.f, 0.f};

    {
#pragma unroll
        for (int u = 0; u < 8; u++) {
            int linear = u * 256 + tid;
            int r = linear >> 5;
            int c4 = (linear & 31) * 4;
            cpasync16(sb + (uint32_t)(r * KPAD + c4) * 4,
                      &g_k[(size_t)r * DKV + kvh * HDIM + c4]);
            cpasync16(sb + (uint32_t)(TILE_W + r * KPAD + c4) * 4,
                      &g_v[(size_t)r * DKV + kvh * HDIM + c4]);
        }
        CP_COMMIT();
    }

    const int lA = 4 * g + (q >> 1);
    const int lB = lA + 2;
    const bool bq = (q & 1);

    for (int kt = 0; kt <= qt; kt++) {
        const int st = kt & 1;
        if (kt < qt) {
            const int k0n = (kt + 1) * 64;
            const uint32_t basew = (uint32_t)((st ^ 1) * 2 * TILE_W);
#pragma unroll
            for (int u = 0; u < 8; u++) {
                int linear = u * 256 + tid;
                int r = linear >> 5;
                int c4 = (linear & 31) * 4;
                cpasync16(sb + (basew + r * KPAD + c4) * 4,
                          &g_k[(size_t)(k0n + r) * DKV + kvh * HDIM + c4]);
                cpasync16(sb + (basew + TILE_W + r * KPAD + c4) * 4,
                          &g_v[(size_t)(k0n + r) * DKV + kvh * HDIM + c4]);
            }
            CP_COMMIT();
            CP_WAIT(1);
        } else {
            CP_WAIT(0);
        }
        __syncthreads();

        const uint32_t* Ksb = smw + st * 2 * TILE_W;
        const uint32_t* Vsb = Ksb + TILE_W;

        float sacc[8][4];
#pragma unroll
        for (int n = 0; n < 8; n++) {
#pragma unroll
            for (int c = 0; c < 4; c++) sacc[n][c] = 0.f;
            const uint32_t* bb = Ksb + (n * 8 + g) * KPAD + q;
#pragma unroll
            for (int kk = 0; kk < 16; kk++) {
                uint32_t b0 = bb[kk * 8];
                uint32_t b1 = bb[kk * 8 + 4];
                mma8(sacc[n], qf[kk], b0, b1);
            }
        }

        if (kt == qt) {
#pragma unroll
            for (int n = 0; n < 8; n++) {
                const int col0 = n * 8 + 2 * q;
                const int rA = m0 + g, rB = m0 + g + 8;
                if (col0 > rA) sacc[n][0] = -1e30f;
                if (col0 + 1 > rA) sacc[n][1] = -1e30f;
                if (col0 > rB) sacc[n][2] = -1e30f;
                if (col0 + 1 > rB) sacc[n][3] = -1e30f;
            }
        }

        float mx0 = -1e30f, mx1 = -1e30f;
#pragma unroll
        for (int n = 0; n < 8; n++) {
            mx0 = fmaxf(mx0, fmaxf(sacc[n][0], sacc[n][1]));
            mx1 = fmaxf(mx1, fmaxf(sacc[n][2], sacc[n][3]));
        }
        mx0 = fmaxf(mx0, __shfl_xor_sync(0xffffffffu, mx0, 1));
        mx0 = fmaxf(mx0, __shfl_xor_sync(0xffffffffu, mx0, 2));
        mx1 = fmaxf(mx1, __shfl_xor_sync(0xffffffffu, mx1, 1));
        mx1 = fmaxf(mx1, __shfl_xor_sync(0xffffffffu, mx1, 2));

        const float nm0 = fmaxf(mrow[0], mx0);
        const float nm1 = fmaxf(mrow[1], mx1);
        const float corr0 = exp2f(mrow[0] - nm0);
        const float corr1 = exp2f(mrow[1] - nm1);
        float rs0 = 0.f, rs1 = 0.f;
#pragma unroll
        for (int n = 0; n < 8; n++) {
            sacc[n][0] = exp2f(sacc[n][0] - nm0);
            sacc[n][1] = exp2f(sacc[n][1] - nm0);
            sacc[n][2] = exp2f(sacc[n][2] - nm1);
            sacc[n][3] = exp2f(sacc[n][3] - nm1);
            rs0 += sacc[n][0] + sacc[n][1];
            rs1 += sacc[n][2] + sacc[n][3];
        }
        rs0 += __shfl_xor_sync(0xffffffffu, rs0, 1);
        rs0 += __shfl_xor_sync(0xffffffffu, rs0, 2);
        rs1 += __shfl_xor_sync(0xffffffffu, rs1, 1);
        rs1 += __shfl_xor_sync(0xffffffffu, rs1, 2);
        lrow[0] = lrow[0] * corr0 + rs0;
        lrow[1] = lrow[1] * corr1 + rs1;
        mrow[0] = nm0;
        mrow[1] = nm1;
#pragma unroll
        for (int n = 0; n < 16; n++) {
            oacc[n][0] *= corr0;
            oacc[n][1] *= corr0;
            oacc[n][2] *= corr1;
            oacc[n][3] *= corr1;
        }

#pragma unroll
        for (int kk = 0; kk < 8; kk++) {
            float v0 = __shfl_sync(0xffffffffu, sacc[kk][0], lA);
            float v1 = __shfl_sync(0xffffffffu, sacc[kk][1], lA);
            float v2 = __shfl_sync(0xffffffffu, sacc[kk][2], lA);
            float v3 = __shfl_sync(0xffffffffu, sacc[kk][3], lA);
            float w0 = __shfl_sync(0xffffffffu, sacc[kk][0], lB);
            float w1 = __shfl_sync(0xffffffffu, sacc[kk][1], lB);
            float w2 = __shfl_sync(0xffffffffu, sacc[kk][2], lB);
            float w3 = __shfl_sync(0xffffffffu, sacc[kk][3], lB);
            uint32_t pa[4];
            pa[0] = f2tf(bq ? v1 : v0);
            pa[1] = f2tf(bq ? v3 : v2);
            pa[2] = f2tf(bq ? w1 : w0);
            pa[3] = f2tf(bq ? w3 : w2);
            const uint32_t* vb = Vsb + (kk * 8 + q) * KPAD + g;
#pragma unroll
            for (int n = 0; n < 16; n++) {
                uint32_t b0 = vb[n * 8];
                uint32_t b1 = vb[4 * KPAD + n * 8];
                mma8(oacc[n], pa, b0, b1);
            }
        }
        __syncthreads();
    }

    // ---- write O (tf32-rounded: it is the A operand of the Wo GEMM) ----
    const float inv0 = 1.f / lrow[0];
    const float inv1 = 1.f / lrow[1];
    const int rowA = q0 + m0 + g;
    const int rowB = rowA + 8;
#pragma unroll
    for (int n = 0; n < 16; n++) {
        const int col = h * HDIM + n * 8 + 2 * q;
        *(float2*)&g_attn[(size_t)rowA * DQ + col] = make_float2(
            __uint_as_float(f2tf(oacc[n][0] * inv0)),
            __uint_as_float(f2tf(oacc[n][1] * inv0)));
        *(float2*)&g_attn[(size_t)rowB * DQ + col] = make_float2(
            __uint_as_float(f2tf(oacc[n][2] * inv1)),
            __uint_as_float(f2tf(oacc[n][3] * inv1)));
    }
}

// ------------------- host launch -------------------
extern "C" void kernel_launch(void* const* d_in, const int* in_sizes, int n_in,
                              void* d_out, int out_size) {
    const float* X   = (const float*)d_in[0];
    const float* Wq  = (const float*)d_in[1];
    const float* Wk  = (const float*)d_in[2];
    const float* Wv  = (const float*)d_in[3];
    const float* Wo  = (const float*)d_in[4];
    const float* Wr1 = (const float*)d_in[5];
    const float* br1 = (const float*)d_in[6];
    const float* Wr2 = (const float*)d_in[7];
    const float* br2 = (const float*)d_in[8];
    float* out = (float*)d_out;

    float *p_q, *p_h, *p_fused, *p_k, *p_v, *p_attn;
    float *p_xr, *p_wq, *p_wk, *p_wv, *p_wo, *p_wr1;
    cudaGetSymbolAddress((void**)&p_q, g_q);
    cudaGetSymbolAddress((void**)&p_h, g_h);
    cudaGetSymbolAddress((void**)&p_fused, g_fused);
    cudaGetSymbolAddress((void**)&p_k, g_k);
    cudaGetSymbolAddress((void**)&p_v, g_v);
    cudaGetSymbolAddress((void**)&p_attn, g_attn);
    cudaGetSymbolAddress((void**)&p_xr, g_xr);
    cudaGetSymbolAddress((void**)&p_wq, g_wq);
    cudaGetSymbolAddress((void**)&p_wk, g_wk);
    cudaGetSymbolAddress((void**)&p_wv, g_wv);
    cudaGetSymbolAddress((void**)&p_wo, g_wo);
    cudaGetSymbolAddress((void**)&p_wr1, g_wr1);

    cudaFuncSetAttribute(attn_kernel, cudaFuncAttributeMaxDynamicSharedMemorySize, ATTN_SMEM_BYTES);
    cudaFuncSetAttribute(mm3<0>, cudaFuncAttributeMaxDynamicSharedMemorySize, MM_SMEM_BYTES);
    cudaFuncSetAttribute(mm3<1>, cudaFuncAttributeMaxDynamicSharedMemorySize, MM_SMEM_BYTES);
    cudaFuncSetAttribute(mm3<2>, cudaFuncAttributeMaxDynamicSharedMemorySize, MM_SMEM_BYTES);
    cudaFuncSetAttribute(mm3_kv, cudaFuncAttributeMaxDynamicSharedMemorySize, MM_SMEM_BYTES);

    // RoPE freq table + weight pre-rounding (tf32)
    freq_kernel<<<1, 64>>>();
    round4_kernel<<<(DD * DQ) / 1024, 256>>>(Wq, p_wq);
    round4_kernel<<<(DD * DKV) / 1024, 256>>>(Wk, p_wk);
    round4_kernel<<<(DD * DKV) / 1024, 256>>>(Wv, p_wv);
    round4_kernel<<<(DQ * DD) / 1024, 256>>>(Wo, p_wo);
    round4_kernel<<<(DD * RDIM) / 1024, 256>>>(Wr1, p_wr1);

    // EMA (also emits X_r)
    ema_local_kernel<<<(EMA_NC * DD / 4) / 256, 256>>>(X);
    ema_scan_kernel<<<2, 256>>>();
    ema_fix_kernel<<<((EMA_NC - 1) * DD / 4) / 256, 256>>>();

    // q = X @ Wq (pre-rounded output: A of Wr1 GEMM)
    mm3<2><<<dim3(DQ / 128, TT / 128), 256, MM_SMEM_BYTES>>>(p_xr, p_wq, nullptr, p_q, DQ, DD);
    // h = silu(q @ Wr1 + br1)
    mm3<1><<<dim3(RDIM / 128, TT / 128), 256, MM_SMEM_BYTES>>>(p_q, p_wr1, br1, p_h, RDIM, DQ);
    // lam + fused (stores rounded)
    router_fused_kernel<<<TT, 256>>>(X, Wr2, br2);
    // k, v fused launch (both rounded outputs)
    mm3_kv<<<dim3(2 * DKV / 128, TT / 128), 256, MM_SMEM_BYTES>>>(p_fused, p_wk, p_wv, p_k, p_v, DD);
    // RoPE: q gets softmax scale * log2e folded in; k plain
    rope_kernel<<<TT, 256>>>(p_q, DQ, NH, ATTN_SCALE * LOG2E);
    rope_kernel<<<TT, 256>>>(p_k, DKV, NKV, 1.0f);
    // attention
    attn_kernel<<<dim3(TT / 64, NH / 2), 256, ATTN_SMEM_BYTES>>>();
    // out = attn @ Wo
    mm3<0><<<dim3(DD / 128, TT / 128), 256, MM_SMEM_BYTES>>>(p_attn, p_wo, nullptr, out, DD, DQ);
}